// round 1
// baseline (speedup 1.0000x reference)
#include <cuda_runtime.h>
#include <math.h>

#define NRES 10000
#define KNN 30
#define HDIM 32
#define NLAYERS 4
#define EFD 32
#define NEDGE (NRES*KNN)

// ---------------- device scratch (allocation-free rule: __device__ globals) ----------------
__device__ float g_h0[2][NRES*HDIM];
__device__ float g_h1[2][NRES*3*HDIM];
__device__ float g_ef[NEDGE*EFD];      // per-edge edge features (updated per layer)
__device__ float g_R[NEDGE*9];         // per-edge rotation, rows x,y,z
__device__ int   g_src[NEDGE];
__device__ float g_xca[NRES*3];
__device__ float g_sq[NRES];
__device__ int   g_bstart[8];
__device__ int   g_bend[8];

__constant__ int c_aa[87] = {
  0,
  1,1,1,1,1,1,1,
  2,2,2,2,
  3,3,3,3,
  4,4,
  5,5,5,5,5,
  6,6,6,6,6,
  8,8,8,8,8,8,
  9,9,9,9,
  10,10,10,10,
  11,11,11,11,11,
  12,12,12,12,
  13,13,13,13,13,13,13,
  14,14,14,
  15,15,
  16,16,16,
  17,17,17,17,17,17,17,17,17,17,
  18,18,18,18,18,18,18,18,
  19,19,19
};
__constant__ int c_off[87] = {
  0,
  0,1,2,3,4,5,6,
  0,1,2,3,
  0,1,2,3,
  0,1,
  0,1,2,3,4,
  0,1,2,3,4,
  0,1,2,3,4,5,
  0,1,2,3,
  0,1,2,3,
  0,1,2,3,4,
  0,1,2,3,
  0,1,2,3,4,5,6,
  0,1,2,
  0,1,
  0,1,2,
  0,1,2,3,4,5,6,7,8,9,
  0,1,2,3,4,5,6,7,
  0,1,2
};

__device__ __forceinline__ float fin0(float v){ return isfinite(v) ? v : 0.f; }

// ---------------- batch ranges ----------------
__global__ void init_ranges_kernel(){
  int t = threadIdx.x;
  if (t < 8){ g_bstart[t] = NRES; g_bend[t] = 0; }
}
__global__ void batch_range_kernel(const int* __restrict__ bid){
  int i = blockIdx.x*blockDim.x + threadIdx.x;
  if (i >= NRES) return;
  int b = bid[i];
  atomicMin(&g_bstart[b], i);
  atomicMax(&g_bend[b], i+1);
}

// ---------------- node features + embeddings ----------------
// one warp per node, lane = output channel
__global__ __launch_bounds__(256) void node_embed_kernel(
    const float* __restrict__ bb, const float* __restrict__ lat,
    const float* __restrict__ Wemb0, const float* __restrict__ Wemb1)
{
  int lane = threadIdx.x & 31;
  int i = blockIdx.x*8 + (threadIdx.x >> 5);
  if (i >= NRES) return;

  float ca0 = bb[i*12+3], ca1 = bb[i*12+4], ca2 = bb[i*12+5];
  if (lane == 0){
    g_xca[i*3+0]=ca0; g_xca[i*3+1]=ca1; g_xca[i*3+2]=ca2;
    g_sq[i] = ca0*ca0 + ca1*ca1 + ca2*ca2;
  }

  // dihedrals for D_flat[3i..3i+2] (all lanes compute redundantly; uniform)
  float Dv[3];
  #pragma unroll
  for (int t3 = 0; t3 < 3; t3++){
    int t = 3*i + t3;
    float D = 0.f;
    if (t >= 1 && t <= 3*NRES - 3){
      int d0 = t - 1;
      float x[4][3];
      #pragma unroll
      for (int q = 0; q < 4; q++){
        int m = d0 + q; int r = m/3; int am = m - r*3;
        x[q][0] = bb[r*12 + am*3 + 0];
        x[q][1] = bb[r*12 + am*3 + 1];
        x[q][2] = bb[r*12 + am*3 + 2];
      }
      float u2[3], u1[3], u0[3];
      #pragma unroll
      for (int c = 0; c < 3; c++){ u2[c]=x[1][c]-x[0][c]; u1[c]=x[2][c]-x[1][c]; u0[c]=x[3][c]-x[2][c]; }
      float n2n = sqrtf(u2[0]*u2[0]+u2[1]*u2[1]+u2[2]*u2[2]) + 1e-8f;
      float n1n = sqrtf(u1[0]*u1[0]+u1[1]*u1[1]+u1[2]*u1[2]) + 1e-8f;
      float n0n = sqrtf(u0[0]*u0[0]+u0[1]*u0[1]+u0[2]*u0[2]) + 1e-8f;
      #pragma unroll
      for (int c = 0; c < 3; c++){ u2[c]/=n2n; u1[c]/=n1n; u0[c]/=n0n; }
      float c21[3] = { u2[1]*u1[2]-u2[2]*u1[1], u2[2]*u1[0]-u2[0]*u1[2], u2[0]*u1[1]-u2[1]*u1[0] };
      float c10[3] = { u1[1]*u0[2]-u1[2]*u0[1], u1[2]*u0[0]-u1[0]*u0[2], u1[0]*u0[1]-u1[1]*u0[0] };
      float l21 = sqrtf(c21[0]*c21[0]+c21[1]*c21[1]+c21[2]*c21[2]) + 1e-8f;
      float l10 = sqrtf(c10[0]*c10[0]+c10[1]*c10[1]+c10[2]*c10[2]) + 1e-8f;
      #pragma unroll
      for (int c = 0; c < 3; c++){ c21[c]/=l21; c10[c]/=l10; }
      float cosD = c21[0]*c10[0]+c21[1]*c10[1]+c21[2]*c10[2];
      cosD = fminf(fmaxf(cosD, -1.f + 1e-7f), 1.f - 1e-7f);
      float sdot = u2[0]*c10[0]+u2[1]*c10[1]+u2[2]*c10[2];
      float sgn = (sdot > 0.f) ? 1.f : ((sdot < 0.f) ? -1.f : 0.f);
      D = sgn * acosf(cosD);
    }
    Dv[t3] = D;
  }
  float x0[7] = { cosf(Dv[0]), cosf(Dv[1]), cosf(Dv[2]),
                  sinf(Dv[0]), sinf(Dv[1]), sinf(Dv[2]), 1.f };

  // l1 vector channels (7 x 3)
  float v[7][3];
  #pragma unroll
  for (int a = 0; a < 4; a++){
    v[a][0] = bb[i*12 + a*3 + 0] - ca0;
    v[a][1] = bb[i*12 + a*3 + 1] - ca1;
    v[a][2] = bb[i*12 + a*3 + 2] - ca2;
  }
  // fwdv
  if (i < NRES-1){
    float dx = bb[(i+1)*12+3] - ca0, dy = bb[(i+1)*12+4] - ca1, dz = bb[(i+1)*12+5] - ca2;
    float n = sqrtf(dx*dx+dy*dy+dz*dz) + 1e-8f;
    v[4][0]=dx/n; v[4][1]=dy/n; v[4][2]=dz/n;
  } else { v[4][0]=v[4][1]=v[4][2]=0.f; }
  // bwdv = -f[i-1], f[i-1] = norm(ca[i]-ca[i-1])
  if (i > 0){
    float dx = ca0 - bb[(i-1)*12+3], dy = ca1 - bb[(i-1)*12+4], dz = ca2 - bb[(i-1)*12+5];
    float n = sqrtf(dx*dx+dy*dy+dz*dz) + 1e-8f;
    v[5][0]=-dx/n; v[5][1]=-dy/n; v[5][2]=-dz/n;
  } else { v[5][0]=v[5][1]=v[5][2]=0.f; }
  // vcb
  {
    float b0 = ca0 - bb[i*12+0], b1 = ca1 - bb[i*12+1], b2 = ca2 - bb[i*12+2];
    float cc0 = bb[i*12+6] - ca0, cc1 = bb[i*12+7] - ca1, cc2 = bb[i*12+8] - ca2;
    float a0 = b1*cc2 - b2*cc1, a1 = b2*cc0 - b0*cc2, a2 = b0*cc1 - b1*cc0;
    v[6][0] = -0.58273431f*a0 + 0.56802827f*b0 - 0.54067466f*cc0;
    v[6][1] = -0.58273431f*a1 + 0.56802827f*b1 - 0.54067466f*cc1;
    v[6][2] = -0.58273431f*a2 + 0.56802827f*b2 - 0.54067466f*cc2;
  }
  #pragma unroll
  for (int q = 0; q < 7; q++){
    v[q][0]=fin0(v[q][0]); v[q][1]=fin0(v[q][1]); v[q][2]=fin0(v[q][2]);
  }

  // h0 = relu([dih(7), latent0(32)] @ Wemb0)
  float acc = 0.f;
  #pragma unroll
  for (int d = 0; d < 7; d++) acc = fmaf(x0[d], Wemb0[d*32 + lane], acc);
  for (int d = 0; d < 32; d++) acc = fmaf(lat[(i*4+0)*32 + d], Wemb0[(7+d)*32 + lane], acc);
  g_h0[0][i*32 + lane] = fmaxf(acc, 0.f);

  // h1[j] = [l1_swapped(7), latent[1+j](32)] @ Wemb1
  #pragma unroll
  for (int j = 0; j < 3; j++){
    float a2 = 0.f;
    #pragma unroll
    for (int d = 0; d < 7; d++) a2 = fmaf(v[d][j], Wemb1[d*32 + lane], a2);
    for (int d = 0; d < 32; d++) a2 = fmaf(lat[(i*4+1+j)*32 + d], Wemb1[(7+d)*32 + lane], a2);
    g_h1[0][(i*3+j)*32 + lane] = a2;
  }
}

// ---------------- kNN: one block per row ----------------
__global__ __launch_bounds__(256) void knn_kernel(const int* __restrict__ bid){
  int i = blockIdx.x;
  int tid = threadIdx.x;
  float xi0 = g_xca[i*3+0], xi1 = g_xca[i*3+1], xi2 = g_xca[i*3+2];
  float sqi = g_sq[i];
  int b = bid[i];
  int lo = g_bstart[b], hi = g_bend[b];

  float ld[KNN]; int li[KNN];
  #pragma unroll
  for (int k = 0; k < KNN; k++){ ld[k] = 3.0e38f; li[k] = 0x7fffffff; }

  for (int j = lo + tid; j < hi; j += 256){
    if (j == i) continue;
    float dot = xi0*g_xca[j*3+0] + xi1*g_xca[j*3+1] + xi2*g_xca[j*3+2];
    float d2 = sqi + g_sq[j] - 2.f*dot;
    float wD = ld[KNN-1]; int wI = li[KNN-1];
    if (d2 > wD || (d2 == wD && j > wI)) continue;
    int p = KNN-1;
    while (p > 0 && (ld[p-1] > d2 || (ld[p-1] == d2 && li[p-1] > j))){
      ld[p] = ld[p-1]; li[p] = li[p-1]; p--;
    }
    ld[p] = d2; li[p] = j;
  }
  __syncthreads();

  __shared__ float sd[256];
  __shared__ int   si2[256];
  __shared__ int   so2[256];
  int p = 0;
  for (int k = 0; k < KNN; k++){
    sd[tid]  = (p < KNN) ? ld[p] : 3.0e38f;
    si2[tid] = (p < KNN) ? li[p] : 0x7fffffff;
    so2[tid] = tid;
    __syncthreads();
    for (int off = 128; off > 0; off >>= 1){
      if (tid < off){
        float dB = sd[tid+off]; int iB = si2[tid+off];
        if (dB < sd[tid] || (dB == sd[tid] && iB < si2[tid])){
          sd[tid] = dB; si2[tid] = iB; so2[tid] = so2[tid+off];
        }
      }
      __syncthreads();
    }
    if (tid == 0){
      int w = si2[0];
      g_src[i*KNN + k] = (w == 0x7fffffff) ? i : w;  // safety
    }
    int win = so2[0];
    __syncthreads();
    if (tid == win) p++;
    __syncthreads();
  }
}

// ---------------- edge init: ef + R ----------------
__global__ void edge_init_kernel(){
  int e = blockIdx.x*blockDim.x + threadIdx.x;
  if (e >= NEDGE) return;
  int i = e / KNN;
  int s = g_src[e];
  float vx = g_xca[i*3+0] - g_xca[s*3+0];
  float vy = g_xca[i*3+1] - g_xca[s*3+1];
  float vz = g_xca[i*3+2] - g_xca[s*3+2];
  float dist = sqrtf(vx*vx + vy*vy + vz*vz);
  float* ef = &g_ef[e*EFD];
  #pragma unroll
  for (int j = 0; j < 16; j++){
    float mu = (float)j * (20.f/15.f);
    float t = (dist - mu) / 1.25f;
    ef[j] = expf(-t*t);
  }
  float diff = (float)(s - i);
  #pragma unroll
  for (int f = 0; f < 8; f++){
    float fr = expf(-((float)(2*f)/16.f) * 9.210340371976184f);
    float a = diff * fr;
    ef[16+f] = cosf(a);
    ef[24+f] = sinf(a);
  }
  // R: z = norm(vec), a = |z0|<0.9 ? ex : ey, x = norm(cross(a,z)), y = cross(z,x)
  float nz = dist + 1e-8f;
  float z0 = vx/nz, z1 = vy/nz, z2 = vz/nz;
  float a0, a1, a2;
  if (fabsf(z0) < 0.9f){ a0=1.f; a1=0.f; a2=0.f; } else { a0=0.f; a1=1.f; a2=0.f; }
  float cx0 = a1*z2 - a2*z1, cx1 = a2*z0 - a0*z2, cx2 = a0*z1 - a1*z0;
  float nx = sqrtf(cx0*cx0 + cx1*cx1 + cx2*cx2) + 1e-8f;
  float x0 = cx0/nx, x1 = cx1/nx, x2 = cx2/nx;
  float y0 = z1*x2 - z2*x1, y1 = z2*x0 - z0*x2, y2 = z0*x1 - z1*x0;
  float* R = &g_R[e*9];
  R[0]=x0; R[1]=x1; R[2]=x2;
  R[3]=y0; R[4]=y1; R[5]=y2;
  R[6]=z0; R[7]=z1; R[8]=z2;
}

// ---------------- message passing phase 1: messages + node update ----------------
__global__ __launch_bounds__(256) void mp_phase1(int bufIn,
    const float* __restrict__ We1, const float* __restrict__ Wss, const float* __restrict__ Wds,
    const float* __restrict__ We2, const float* __restrict__ Wvs, const float* __restrict__ W0,
    const float* __restrict__ W1)
{
  __shared__ float sWe1[1024], sWss[1024], sWds[1024], sWe2[1024], sWvs[1024], sW0[1024], sW1[1024];
  for (int t = threadIdx.x; t < 1024; t += 256){
    sWe1[t]=We1[t]; sWss[t]=Wss[t]; sWds[t]=Wds[t]; sWe2[t]=We2[t];
    sWvs[t]=Wvs[t]; sW0[t]=W0[t]; sW1[t]=W1[t];
  }
  __syncthreads();
  const float* h0in = g_h0[bufIn];  float* h0out = g_h0[bufIn^1];
  const float* h1in = g_h1[bufIn];  float* h1out = g_h1[bufIn^1];
  int lane = threadIdx.x & 31;
  for (int i = blockIdx.x*8 + (threadIdx.x >> 5); i < NRES; i += gridDim.x*8){
    float h0d = h0in[i*HDIM + lane];
    float hd = 0.f;
    #pragma unroll
    for (int d = 0; d < 32; d++) hd = fmaf(__shfl_sync(0xffffffffu, h0d, d), sWds[d*32+lane], hd);
    float acc0 = 0.f, av0 = 0.f, av1 = 0.f, av2 = 0.f;
    for (int k = 0; k < KNN; k++){
      int e = i*KNN + k;
      int s = g_src[e];
      float efc = g_ef[e*EFD + lane];
      float h0s = h0in[s*HDIM + lane];
      float t = hd;
      #pragma unroll
      for (int d = 0; d < 32; d++){
        t = fmaf(__shfl_sync(0xffffffffu, efc, d), sWe1[d*32+lane], t);
        t = fmaf(__shfl_sync(0xffffffffu, h0s, d), sWss[d*32+lane], t);
      }
      t = fmaxf(t, 0.f);
      float g = 0.f;
      #pragma unroll
      for (int d = 0; d < 32; d++) g = fmaf(__shfl_sync(0xffffffffu, t, d), sWe2[d*32+lane], g);
      acc0 = fmaf(g, h0s, acc0);
      float h1s0 = h1in[(s*3+0)*HDIM + lane];
      float h1s1 = h1in[(s*3+1)*HDIM + lane];
      float h1s2 = h1in[(s*3+2)*HDIM + lane];
      const float* Re = &g_R[e*9];
      float r0=Re[0],r1=Re[1],r2=Re[2],r3=Re[3],r4=Re[4],r5=Re[5],r6=Re[6],r7=Re[7],r8=Re[8];
      float vr0 = r0*h1s0 + r1*h1s1 + r2*h1s2;
      float vr1 = r3*h1s0 + r4*h1s1 + r5*h1s2;
      float vr2 = r6*h1s0 + r7*h1s1 + r8*h1s2;
      float w0 = 0.f, w1 = 0.f, w2 = 0.f;
      #pragma unroll
      for (int d = 0; d < 32; d++){
        float wv = sWvs[d*32+lane];
        w0 = fmaf(__shfl_sync(0xffffffffu, vr0, d), wv, w0);
        w1 = fmaf(__shfl_sync(0xffffffffu, vr1, d), wv, w1);
        w2 = fmaf(__shfl_sync(0xffffffffu, vr2, d), wv, w2);
      }
      w0 *= g; w1 *= g; w2 *= g;
      av0 += r0*w0 + r3*w1 + r6*w2;
      av1 += r1*w0 + r4*w1 + r7*w2;
      av2 += r2*w0 + r5*w1 + r8*w2;
    }
    acc0 /= 30.f; av0 /= 30.f; av1 /= 30.f; av2 /= 30.f;
    float u = 0.f;
    #pragma unroll
    for (int d = 0; d < 32; d++) u = fmaf(__shfl_sync(0xffffffffu, acc0, d), sW0[d*32+lane], u);
    h0out[i*HDIM + lane] = h0d + fmaxf(u, 0.f);
    float o0 = 0.f, o1 = 0.f, o2 = 0.f;
    #pragma unroll
    for (int d = 0; d < 32; d++){
      float w = sW1[d*32+lane];
      o0 = fmaf(__shfl_sync(0xffffffffu, av0, d), w, o0);
      o1 = fmaf(__shfl_sync(0xffffffffu, av1, d), w, o1);
      o2 = fmaf(__shfl_sync(0xffffffffu, av2, d), w, o2);
    }
    h1out[(i*3+0)*HDIM + lane] = h1in[(i*3+0)*HDIM + lane] + o0;
    h1out[(i*3+1)*HDIM + lane] = h1in[(i*3+1)*HDIM + lane] + o1;
    h1out[(i*3+2)*HDIM + lane] = h1in[(i*3+2)*HDIM + lane] + o2;
  }
}

// ---------------- message passing phase 2: ef update (uses NEW h0) ----------------
__global__ __launch_bounds__(256) void mp_phase2(int bufH0,
    const float* __restrict__ Wu1, const float* __restrict__ Wu2)
{
  __shared__ float sW1[96*64];
  __shared__ float sW2[64*32];
  for (int t = threadIdx.x; t < 96*64; t += 256) sW1[t] = Wu1[t];
  for (int t = threadIdx.x; t < 64*32; t += 256) sW2[t] = Wu2[t];
  __syncthreads();
  const float* h0 = g_h0[bufH0];
  int lane = threadIdx.x & 31;
  for (int e = blockIdx.x*8 + (threadIdx.x >> 5); e < NEDGE; e += gridDim.x*8){
    int i = e / KNN;
    int s = g_src[e];
    float efc = g_ef[e*EFD + lane];
    float h0s = h0[s*HDIM + lane];
    float h0d = h0[i*HDIM + lane];
    float y0 = 0.f, y1 = 0.f;
    #pragma unroll
    for (int d = 0; d < 32; d++){
      float a = __shfl_sync(0xffffffffu, efc, d);
      float b = __shfl_sync(0xffffffffu, h0s, d);
      float c = __shfl_sync(0xffffffffu, h0d, d);
      y0 = fmaf(a, sW1[d*64 + lane],        y0);
      y0 = fmaf(b, sW1[(32+d)*64 + lane],   y0);
      y0 = fmaf(c, sW1[(64+d)*64 + lane],   y0);
      y1 = fmaf(a, sW1[d*64 + 32 + lane],      y1);
      y1 = fmaf(b, sW1[(32+d)*64 + 32 + lane], y1);
      y1 = fmaf(c, sW1[(64+d)*64 + 32 + lane], y1);
    }
    y0 = fmaxf(y0, 0.f); y1 = fmaxf(y1, 0.f);
    float o = 0.f;
    #pragma unroll
    for (int h = 0; h < 32; h++) o = fmaf(__shfl_sync(0xffffffffu, y0, h), sW2[h*32 + lane], o);
    #pragma unroll
    for (int h = 0; h < 32; h++) o = fmaf(__shfl_sync(0xffffffffu, y1, h), sW2[(32+h)*32 + lane], o);
    g_ef[e*EFD + lane] = efc + o;
  }
}

// ---------------- decode: atoms + seq ----------------
__global__ __launch_bounds__(256) void decode_kernel(int buf,
    const float* __restrict__ rot, const float* __restrict__ trans,
    const float* __restrict__ Wp0, const float* __restrict__ Wt, const float* __restrict__ bt,
    const float* __restrict__ Wseq1, const float* __restrict__ bseq1,
    const float* __restrict__ Wseq2, const float* __restrict__ bseq2,
    const float* __restrict__ Wseq3, const float* __restrict__ bseq3,
    const float* __restrict__ lit_pos, const float* __restrict__ Wchi, const float* __restrict__ Wpsi,
    float* __restrict__ out)
{
  __shared__ float su[8][162];
  int lane = threadIdx.x & 31;
  int w = threadIdx.x >> 5;
  int i = blockIdx.x*8 + w;
  if (i >= NRES) return;

  float h0c = g_h0[buf][i*HDIM + lane];
  // t0 = relu(h0 @ Wp0)
  float t0 = 0.f;
  #pragma unroll
  for (int d = 0; d < 32; d++) t0 = fmaf(__shfl_sync(0xffffffffu, h0c, d), Wp0[d*32 + lane], t0);
  t0 = fmaxf(t0, 0.f);
  // unnorm = t0 @ Wt + bt (162)
  #pragma unroll
  for (int r = 0; r < 6; r++){
    int idx = r*32 + lane;
    int widx = idx < 162 ? idx : 161;
    float u = bt[widx];
    #pragma unroll
    for (int c = 0; c < 32; c++) u = fmaf(__shfl_sync(0xffffffffu, t0, c), Wt[c*162 + widx], u);
    if (idx < 162) su[w][idx] = u;
  }
  __syncwarp();
  // normalize pairs in place: x / ||x + 1e-8||
  for (int j = lane; j < 81; j += 32){
    float a = su[w][2*j], b = su[w][2*j+1];
    float ea = a + 1e-8f, eb = b + 1e-8f;
    float den = sqrtf(ea*ea + eb*eb);
    su[w][2*j]   = a / den;
    su[w][2*j+1] = b / den;
  }
  __syncwarp();
  float p0 = su[w][0], p1 = su[w][1];
  float r00=rot[i*9+0], r01=rot[i*9+1], r02=rot[i*9+2];
  float r10=rot[i*9+3], r11=rot[i*9+4], r12=rot[i*9+5];
  float r20=rot[i*9+6], r21=rot[i*9+7], r22=rot[i*9+8];
  float tr0=trans[i*3+0], tr1=trans[i*3+1], tr2=trans[i*3+2];

  for (int m = lane; m < 91; m += 32){
    int k, a;
    if (m < 4){ k = 0; a = m; }
    else { k = c_aa[m-4]; a = 4 + c_off[m-4]; }
    float chi[8];
    #pragma unroll
    for (int t = 0; t < 4; t++){
      chi[2*t]   = su[w][2*(1 + k*4 + t)];
      chi[2*t+1] = su[w][2*(1 + k*4 + t) + 1];
    }
    float l[3];
    #pragma unroll
    for (int j = 0; j < 3; j++){
      float acc = lit_pos[(k*14 + a)*3 + j];
      #pragma unroll
      for (int c = 0; c < 8; c++) acc = fmaf(chi[c], Wchi[(c*14 + a)*3 + j], acc);
      acc = fmaf(p0, Wpsi[(0*14 + a)*3 + j], acc);
      acc = fmaf(p1, Wpsi[(1*14 + a)*3 + j], acc);
      l[j] = acc;
    }
    float o0 = r00*l[0] + r01*l[1] + r02*l[2] + tr0;
    float o1 = r10*l[0] + r11*l[1] + r12*l[2] + tr1;
    float o2 = r20*l[0] + r21*l[1] + r22*l[2] + tr2;
    out[((size_t)i*91 + m)*3 + 0] = o0 - tr0;
    out[((size_t)i*91 + m)*3 + 1] = o1 - tr1;
    out[((size_t)i*91 + m)*3 + 2] = o2 - tr2;
  }

  // seq head
  float s1a = bseq1[lane], s1b = bseq1[32 + lane];
  #pragma unroll
  for (int d = 0; d < 32; d++){
    float h = __shfl_sync(0xffffffffu, h0c, d);
    s1a = fmaf(h, Wseq1[d*64 + lane],      s1a);
    s1b = fmaf(h, Wseq1[d*64 + 32 + lane], s1b);
  }
  s1a = fmaxf(s1a, 0.f); s1b = fmaxf(s1b, 0.f);
  float s2 = bseq2[lane];
  #pragma unroll
  for (int h = 0; h < 32; h++) s2 = fmaf(__shfl_sync(0xffffffffu, s1a, h), Wseq2[h*32 + lane], s2);
  #pragma unroll
  for (int h = 0; h < 32; h++) s2 = fmaf(__shfl_sync(0xffffffffu, s1b, h), Wseq2[(32+h)*32 + lane], s2);
  s2 = fmaxf(s2, 0.f);
  int ll = lane < 20 ? lane : 19;
  float lg = bseq3[ll];
  #pragma unroll
  for (int c = 0; c < 32; c++) lg = fmaf(__shfl_sync(0xffffffffu, s2, c), Wseq3[c*20 + ll], lg);
  float mv = (lane < 20) ? lg : -3.0e38f;
  #pragma unroll
  for (int o = 16; o > 0; o >>= 1) mv = fmaxf(mv, __shfl_xor_sync(0xffffffffu, mv, o));
  float ex = (lane < 20) ? expf(lg - mv) : 0.f;
  #pragma unroll
  for (int o = 16; o > 0; o >>= 1) ex += __shfl_xor_sync(0xffffffffu, ex, o);
  if (lane < 20) out[(size_t)NRES*273 + (size_t)i*20 + lane] = lg - mv - logf(ex);
}

// ---------------- launch ----------------
extern "C" void kernel_launch(void* const* d_in, const int* in_sizes, int n_in,
                              void* d_out, int out_size)
{
  const float* bb      = (const float*)d_in[0];
  const float* latent  = (const float*)d_in[1];
  const float* rrot    = (const float*)d_in[2];
  const float* rtrans  = (const float*)d_in[3];
  const float* Wemb0   = (const float*)d_in[4];
  const float* Wemb1   = (const float*)d_in[5];
  const float* We1s    = (const float*)d_in[6];
  const float* Wss     = (const float*)d_in[7];
  const float* Wds     = (const float*)d_in[8];
  const float* We2s    = (const float*)d_in[9];
  const float* Wvs     = (const float*)d_in[10];
  const float* W0s     = (const float*)d_in[11];
  const float* W1s     = (const float*)d_in[12];
  const float* Wu1s    = (const float*)d_in[13];
  const float* Wu2s    = (const float*)d_in[14];
  const float* Wp0     = (const float*)d_in[15];
  const float* Wt      = (const float*)d_in[16];
  const float* bt      = (const float*)d_in[17];
  const float* Wseq1   = (const float*)d_in[18];
  const float* bseq1   = (const float*)d_in[19];
  const float* Wseq2   = (const float*)d_in[20];
  const float* bseq2   = (const float*)d_in[21];
  const float* Wseq3   = (const float*)d_in[22];
  const float* bseq3   = (const float*)d_in[23];
  const float* lit_pos = (const float*)d_in[24];
  const float* Wchi    = (const float*)d_in[25];
  const float* Wpsi    = (const float*)d_in[26];
  // d_in[27] = x_mask (all false -> unused)
  const int*   bids    = (const int*)d_in[28];
  float* out = (float*)d_out;

  init_ranges_kernel<<<1, 32>>>();
  batch_range_kernel<<<(NRES+255)/256, 256>>>(bids);
  node_embed_kernel<<<1250, 256>>>(bb, latent, Wemb0, Wemb1);
  knn_kernel<<<NRES, 256>>>(bids);
  edge_init_kernel<<<(NEDGE+255)/256, 256>>>();

  int cur = 0;
  for (int l = 0; l < NLAYERS; l++){
    mp_phase1<<<1250, 256>>>(cur,
        We1s + l*EFD*HDIM, Wss + l*HDIM*HDIM, Wds + l*HDIM*HDIM,
        We2s + l*HDIM*HDIM, Wvs + l*HDIM*HDIM, W0s + l*HDIM*HDIM, W1s + l*HDIM*HDIM);
    mp_phase2<<<2048, 256>>>(cur ^ 1, Wu1s + l*96*64, Wu2s + l*64*32);
    cur ^= 1;
  }

  decode_kernel<<<1250, 256>>>(cur, rrot, rtrans, Wp0, Wt, bt,
                               Wseq1, bseq1, Wseq2, bseq2, Wseq3, bseq3,
                               lit_pos, Wchi, Wpsi, out);
}

// round 2
// speedup vs baseline: 1.7938x; 1.7938x over previous
#include <cuda_runtime.h>
#include <math.h>

#define NRES 10000
#define KNN 30
#define HDIM 32
#define NLAYERS 4
#define EFD 32
#define NEDGE (NRES*KNN)

// ---------------- device scratch ----------------
__device__ float g_h0[2][NRES*HDIM];
__device__ float g_h1[2][NRES*3*HDIM];
__device__ float g_ef[NEDGE*EFD];
__device__ int   g_src[NEDGE];
__device__ float4 g_xca4[NRES];           // (x,y,z,|x|^2)
__device__ int   g_bstart[8];
__device__ int   g_bend[8];
// per-node precomputes
__device__ float g_hs[NRES*HDIM];         // h0 @ Wss
__device__ float g_hd[NRES*HDIM];         // h0 @ Wds
__device__ float g_hv[NRES*3*HDIM];       // h1 @ Wvs
__device__ float g_ps[NRES*64];           // h0new @ Wu1[32:64]
__device__ float g_pd[NRES*64];           // h0new @ Wu1[64:96]

__constant__ int c_aa[87] = {
  0,
  1,1,1,1,1,1,1, 2,2,2,2, 3,3,3,3, 4,4, 5,5,5,5,5, 6,6,6,6,6,
  8,8,8,8,8,8, 9,9,9,9, 10,10,10,10, 11,11,11,11,11, 12,12,12,12,
  13,13,13,13,13,13,13, 14,14,14, 15,15, 16,16,16,
  17,17,17,17,17,17,17,17,17,17, 18,18,18,18,18,18,18,18, 19,19,19
};
__constant__ int c_off[87] = {
  0,
  0,1,2,3,4,5,6, 0,1,2,3, 0,1,2,3, 0,1, 0,1,2,3,4, 0,1,2,3,4,
  0,1,2,3,4,5, 0,1,2,3, 0,1,2,3, 0,1,2,3,4, 0,1,2,3,
  0,1,2,3,4,5,6, 0,1,2, 0,1, 0,1,2,
  0,1,2,3,4,5,6,7,8,9, 0,1,2,3,4,5,6,7, 0,1,2
};

__device__ __forceinline__ float fin0(float v){ return isfinite(v) ? v : 0.f; }

// ---------------- batch ranges ----------------
__global__ void init_ranges_kernel(){
  int t = threadIdx.x;
  if (t < 8){ g_bstart[t] = NRES; g_bend[t] = 0; }
}
__global__ void batch_range_kernel(const int* __restrict__ bid){
  int i = blockIdx.x*blockDim.x + threadIdx.x;
  if (i >= NRES) return;
  int b = bid[i];
  atomicMin(&g_bstart[b], i);
  atomicMax(&g_bend[b], i+1);
}

// ---------------- node features + embeddings (warp per node, lane=channel) ----------------
__global__ __launch_bounds__(256) void node_embed_kernel(
    const float* __restrict__ bb, const float* __restrict__ lat,
    const float* __restrict__ Wemb0, const float* __restrict__ Wemb1)
{
  int lane = threadIdx.x & 31;
  int i = blockIdx.x*8 + (threadIdx.x >> 5);
  if (i >= NRES) return;

  float ca0 = bb[i*12+3], ca1 = bb[i*12+4], ca2 = bb[i*12+5];
  if (lane == 0){
    g_xca4[i] = make_float4(ca0, ca1, ca2, ca0*ca0 + ca1*ca1 + ca2*ca2);
  }

  float Dv[3];
  #pragma unroll
  for (int t3 = 0; t3 < 3; t3++){
    int t = 3*i + t3;
    float D = 0.f;
    if (t >= 1 && t <= 3*NRES - 3){
      int d0 = t - 1;
      float x[4][3];
      #pragma unroll
      for (int q = 0; q < 4; q++){
        int m = d0 + q; int r = m/3; int am = m - r*3;
        x[q][0] = bb[r*12 + am*3 + 0];
        x[q][1] = bb[r*12 + am*3 + 1];
        x[q][2] = bb[r*12 + am*3 + 2];
      }
      float u2[3], u1[3], u0[3];
      #pragma unroll
      for (int c = 0; c < 3; c++){ u2[c]=x[1][c]-x[0][c]; u1[c]=x[2][c]-x[1][c]; u0[c]=x[3][c]-x[2][c]; }
      float n2n = sqrtf(u2[0]*u2[0]+u2[1]*u2[1]+u2[2]*u2[2]) + 1e-8f;
      float n1n = sqrtf(u1[0]*u1[0]+u1[1]*u1[1]+u1[2]*u1[2]) + 1e-8f;
      float n0n = sqrtf(u0[0]*u0[0]+u0[1]*u0[1]+u0[2]*u0[2]) + 1e-8f;
      #pragma unroll
      for (int c = 0; c < 3; c++){ u2[c]/=n2n; u1[c]/=n1n; u0[c]/=n0n; }
      float c21[3] = { u2[1]*u1[2]-u2[2]*u1[1], u2[2]*u1[0]-u2[0]*u1[2], u2[0]*u1[1]-u2[1]*u1[0] };
      float c10[3] = { u1[1]*u0[2]-u1[2]*u0[1], u1[2]*u0[0]-u1[0]*u0[2], u1[0]*u0[1]-u1[1]*u0[0] };
      float l21 = sqrtf(c21[0]*c21[0]+c21[1]*c21[1]+c21[2]*c21[2]) + 1e-8f;
      float l10 = sqrtf(c10[0]*c10[0]+c10[1]*c10[1]+c10[2]*c10[2]) + 1e-8f;
      #pragma unroll
      for (int c = 0; c < 3; c++){ c21[c]/=l21; c10[c]/=l10; }
      float cosD = c21[0]*c10[0]+c21[1]*c10[1]+c21[2]*c10[2];
      cosD = fminf(fmaxf(cosD, -1.f + 1e-7f), 1.f - 1e-7f);
      float sdot = u2[0]*c10[0]+u2[1]*c10[1]+u2[2]*c10[2];
      float sgn = (sdot > 0.f) ? 1.f : ((sdot < 0.f) ? -1.f : 0.f);
      D = sgn * acosf(cosD);
    }
    Dv[t3] = D;
  }
  float x0[7] = { cosf(Dv[0]), cosf(Dv[1]), cosf(Dv[2]),
                  sinf(Dv[0]), sinf(Dv[1]), sinf(Dv[2]), 1.f };

  float v[7][3];
  #pragma unroll
  for (int a = 0; a < 4; a++){
    v[a][0] = bb[i*12 + a*3 + 0] - ca0;
    v[a][1] = bb[i*12 + a*3 + 1] - ca1;
    v[a][2] = bb[i*12 + a*3 + 2] - ca2;
  }
  if (i < NRES-1){
    float dx = bb[(i+1)*12+3] - ca0, dy = bb[(i+1)*12+4] - ca1, dz = bb[(i+1)*12+5] - ca2;
    float n = sqrtf(dx*dx+dy*dy+dz*dz) + 1e-8f;
    v[4][0]=dx/n; v[4][1]=dy/n; v[4][2]=dz/n;
  } else { v[4][0]=v[4][1]=v[4][2]=0.f; }
  if (i > 0){
    float dx = ca0 - bb[(i-1)*12+3], dy = ca1 - bb[(i-1)*12+4], dz = ca2 - bb[(i-1)*12+5];
    float n = sqrtf(dx*dx+dy*dy+dz*dz) + 1e-8f;
    v[5][0]=-dx/n; v[5][1]=-dy/n; v[5][2]=-dz/n;
  } else { v[5][0]=v[5][1]=v[5][2]=0.f; }
  {
    float b0 = ca0 - bb[i*12+0], b1 = ca1 - bb[i*12+1], b2 = ca2 - bb[i*12+2];
    float cc0 = bb[i*12+6] - ca0, cc1 = bb[i*12+7] - ca1, cc2 = bb[i*12+8] - ca2;
    float a0 = b1*cc2 - b2*cc1, a1 = b2*cc0 - b0*cc2, a2 = b0*cc1 - b1*cc0;
    v[6][0] = -0.58273431f*a0 + 0.56802827f*b0 - 0.54067466f*cc0;
    v[6][1] = -0.58273431f*a1 + 0.56802827f*b1 - 0.54067466f*cc1;
    v[6][2] = -0.58273431f*a2 + 0.56802827f*b2 - 0.54067466f*cc2;
  }
  #pragma unroll
  for (int q = 0; q < 7; q++){
    v[q][0]=fin0(v[q][0]); v[q][1]=fin0(v[q][1]); v[q][2]=fin0(v[q][2]);
  }

  float acc = 0.f;
  #pragma unroll
  for (int d = 0; d < 7; d++) acc = fmaf(x0[d], Wemb0[d*32 + lane], acc);
  for (int d = 0; d < 32; d++) acc = fmaf(lat[(i*4+0)*32 + d], Wemb0[(7+d)*32 + lane], acc);
  g_h0[0][i*32 + lane] = fmaxf(acc, 0.f);

  #pragma unroll
  for (int j = 0; j < 3; j++){
    float a2 = 0.f;
    #pragma unroll
    for (int d = 0; d < 7; d++) a2 = fmaf(v[d][j], Wemb1[d*32 + lane], a2);
    for (int d = 0; d < 32; d++) a2 = fmaf(lat[(i*4+1+j)*32 + d], Wemb1[(7+d)*32 + lane], a2);
    g_h1[0][(i*3+j)*32 + lane] = a2;
  }
}

// ---------------- kNN: one WARP per row, shfl-merge ----------------
__global__ __launch_bounds__(256) void knn_kernel(const int* __restrict__ bid){
  int lane = threadIdx.x & 31;
  int i = blockIdx.x*8 + (threadIdx.x >> 5);
  if (i >= NRES) return;
  float4 qi = g_xca4[i];
  int b = bid[i];
  int lo = g_bstart[b], hi = g_bend[b];

  float ld[KNN]; int li[KNN];
  #pragma unroll
  for (int k = 0; k < KNN; k++){ ld[k] = 3.0e38f; li[k] = 0x7fffffff; }

  for (int j = lo + lane; j < hi; j += 32){
    if (j == i) continue;
    float4 qj = g_xca4[j];
    float d2 = qi.w + qj.w - 2.f*(qi.x*qj.x + qi.y*qj.y + qi.z*qj.z);
    float wD = ld[KNN-1]; int wI = li[KNN-1];
    if (d2 > wD || (d2 == wD && j > wI)) continue;
    int p = KNN-1;
    while (p > 0 && (ld[p-1] > d2 || (ld[p-1] == d2 && li[p-1] > j))){
      ld[p] = ld[p-1]; li[p] = li[p-1]; p--;
    }
    ld[p] = d2; li[p] = j;
  }

  // warp merge: 30 rounds of lexicographic argmin over lane heads
  int p = 0;
  float myd = ld[0]; int myi = li[0];
  #pragma unroll 1
  for (int k = 0; k < KNN; k++){
    float bd = myd; int bi = myi; int bl = lane;
    #pragma unroll
    for (int off = 16; off > 0; off >>= 1){
      float od = __shfl_xor_sync(0xffffffffu, bd, off);
      int   oi = __shfl_xor_sync(0xffffffffu, bi, off);
      int   ol = __shfl_xor_sync(0xffffffffu, bl, off);
      if (od < bd || (od == bd && oi < bi)){ bd = od; bi = oi; bl = ol; }
    }
    if (lane == 0) g_src[i*KNN + k] = (bi == 0x7fffffff) ? i : bi;
    if (lane == bl){
      p++;
      myd = (p < KNN) ? ld[p] : 3.0e38f;
      myi = (p < KNN) ? li[p] : 0x7fffffff;
    }
  }
}

// ---------------- edge init: ef only (no R needed!) ----------------
__global__ void edge_init_kernel(){
  int e = blockIdx.x*blockDim.x + threadIdx.x;
  if (e >= NEDGE) return;
  int i = e / KNN;
  int s = g_src[e];
  float4 qi = g_xca4[i], qs = g_xca4[s];
  float vx = qi.x - qs.x, vy = qi.y - qs.y, vz = qi.z - qs.z;
  float dist = sqrtf(vx*vx + vy*vy + vz*vz);
  float* ef = &g_ef[e*EFD];
  #pragma unroll
  for (int j = 0; j < 16; j++){
    float mu = (float)j * (20.f/15.f);
    float t = (dist - mu) / 1.25f;
    ef[j] = expf(-t*t);
  }
  float diff = (float)(s - i);
  #pragma unroll
  for (int f = 0; f < 8; f++){
    float fr = expf(-((float)(2*f)/16.f) * 9.210340371976184f);
    float a = diff * fr;
    ef[16+f] = cosf(a);
    ef[24+f] = sinf(a);
  }
}

// ---------------- per-node precompute: hs = h0@Wss, hd = h0@Wds, hv = h1@Wvs ----------------
__global__ __launch_bounds__(256) void precompA_kernel(int buf,
    const float* __restrict__ Wss, const float* __restrict__ Wds, const float* __restrict__ Wvs)
{
  __shared__ float sWss[1024], sWds[1024], sWvs[1024];
  for (int t = threadIdx.x; t < 1024; t += 256){ sWss[t]=Wss[t]; sWds[t]=Wds[t]; sWvs[t]=Wvs[t]; }
  __syncthreads();
  int lane = threadIdx.x & 31;
  int i = blockIdx.x*8 + (threadIdx.x >> 5);
  if (i >= NRES) return;
  float h0 = g_h0[buf][i*32 + lane];
  float hs0 = 0.f, hs1 = 0.f, hd0 = 0.f, hd1 = 0.f;
  #pragma unroll
  for (int d = 0; d < 32; d += 2){
    float a = __shfl_sync(0xffffffffu, h0, d);
    float b = __shfl_sync(0xffffffffu, h0, d+1);
    hs0 = fmaf(a, sWss[d*32+lane], hs0);     hs1 = fmaf(b, sWss[(d+1)*32+lane], hs1);
    hd0 = fmaf(a, sWds[d*32+lane], hd0);     hd1 = fmaf(b, sWds[(d+1)*32+lane], hd1);
  }
  g_hs[i*32+lane] = hs0 + hs1;
  g_hd[i*32+lane] = hd0 + hd1;
  #pragma unroll
  for (int c = 0; c < 3; c++){
    float h1 = g_h1[buf][(i*3+c)*32 + lane];
    float a0 = 0.f, a1 = 0.f;
    #pragma unroll
    for (int d = 0; d < 32; d += 2){
      a0 = fmaf(__shfl_sync(0xffffffffu, h1, d),   sWvs[d*32+lane],     a0);
      a1 = fmaf(__shfl_sync(0xffffffffu, h1, d+1), sWvs[(d+1)*32+lane], a1);
    }
    g_hv[i*96 + c*32 + lane] = a0 + a1;
  }
}

// ---------------- phase 1: edge messages + node update + fused ps/pd precompute ----------------
__global__ __launch_bounds__(256) void mp_phase1(int bufIn,
    const float* __restrict__ We1, const float* __restrict__ We2,
    const float* __restrict__ W0,  const float* __restrict__ W1,
    const float* __restrict__ Wu1)
{
  __shared__ float sWe1[1024], sWe2[1024], sW0[1024], sW1[1024];
  __shared__ float sU1b[2048], sU1c[2048];
  for (int t = threadIdx.x; t < 1024; t += 256){
    sWe1[t]=We1[t]; sWe2[t]=We2[t]; sW0[t]=W0[t]; sW1[t]=W1[t];
  }
  for (int t = threadIdx.x; t < 2048; t += 256){
    sU1b[t] = Wu1[2048 + t];   // rows 32..63
    sU1c[t] = Wu1[4096 + t];   // rows 64..95
  }
  __syncthreads();
  const float* h0in = g_h0[bufIn];  float* h0out = g_h0[bufIn^1];
  const float* h1in = g_h1[bufIn];  float* h1out = g_h1[bufIn^1];
  int lane = threadIdx.x & 31;
  int i = blockIdx.x*8 + (threadIdx.x >> 5);
  if (i >= NRES) return;

  float h0d = h0in[i*HDIM + lane];
  float hd  = g_hd[i*HDIM + lane];
  float acc0 = 0.f, av0 = 0.f, av1 = 0.f, av2 = 0.f;

  #pragma unroll 2
  for (int k = 0; k < KNN; k++){
    int e = i*KNN + k;
    int s = g_src[e];
    float efc = g_ef[e*EFD + lane];
    float t0 = hd + g_hs[s*HDIM + lane];
    float t1 = 0.f;
    #pragma unroll
    for (int d = 0; d < 32; d += 2){
      t0 = fmaf(__shfl_sync(0xffffffffu, efc, d),   sWe1[d*32+lane],     t0);
      t1 = fmaf(__shfl_sync(0xffffffffu, efc, d+1), sWe1[(d+1)*32+lane], t1);
    }
    float t = fmaxf(t0 + t1, 0.f);
    float g0 = 0.f, g1 = 0.f;
    #pragma unroll
    for (int d = 0; d < 32; d += 2){
      g0 = fmaf(__shfl_sync(0xffffffffu, t, d),   sWe2[d*32+lane],     g0);
      g1 = fmaf(__shfl_sync(0xffffffffu, t, d+1), sWe2[(d+1)*32+lane], g1);
    }
    float g = g0 + g1;
    acc0 = fmaf(g, h0in[s*HDIM + lane], acc0);
    const float* hv = &g_hv[s*96];
    av0 = fmaf(g, hv[lane],      av0);
    av1 = fmaf(g, hv[32+lane],   av1);
    av2 = fmaf(g, hv[64+lane],   av2);
  }
  const float inv = 1.f/(float)KNN;
  acc0 *= inv; av0 *= inv; av1 *= inv; av2 *= inv;

  // h0 update
  float u0 = 0.f, u1 = 0.f;
  #pragma unroll
  for (int d = 0; d < 32; d += 2){
    u0 = fmaf(__shfl_sync(0xffffffffu, acc0, d),   sW0[d*32+lane],     u0);
    u1 = fmaf(__shfl_sync(0xffffffffu, acc0, d+1), sW0[(d+1)*32+lane], u1);
  }
  float h0new = h0d + fmaxf(u0 + u1, 0.f);
  h0out[i*HDIM + lane] = h0new;

  // h1 update
  float o0 = 0.f, o1 = 0.f, o2 = 0.f;
  #pragma unroll
  for (int d = 0; d < 32; d++){
    float w = sW1[d*32+lane];
    o0 = fmaf(__shfl_sync(0xffffffffu, av0, d), w, o0);
    o1 = fmaf(__shfl_sync(0xffffffffu, av1, d), w, o1);
    o2 = fmaf(__shfl_sync(0xffffffffu, av2, d), w, o2);
  }
  h1out[(i*3+0)*HDIM + lane] = h1in[(i*3+0)*HDIM + lane] + o0;
  h1out[(i*3+1)*HDIM + lane] = h1in[(i*3+1)*HDIM + lane] + o1;
  h1out[(i*3+2)*HDIM + lane] = h1in[(i*3+2)*HDIM + lane] + o2;

  // fused phase-2 precompute from h0new: ps = h0new@Wu1[32:64], pd = h0new@Wu1[64:96]
  float psa = 0.f, psb = 0.f, pda = 0.f, pdb = 0.f;
  #pragma unroll
  for (int d = 0; d < 32; d++){
    float h = __shfl_sync(0xffffffffu, h0new, d);
    psa = fmaf(h, sU1b[d*64 + lane],      psa);
    psb = fmaf(h, sU1b[d*64 + 32 + lane], psb);
    pda = fmaf(h, sU1c[d*64 + lane],      pda);
    pdb = fmaf(h, sU1c[d*64 + 32 + lane], pdb);
  }
  g_ps[i*64 + lane]      = psa;
  g_ps[i*64 + 32 + lane] = psb;
  g_pd[i*64 + lane]      = pda;
  g_pd[i*64 + 32 + lane] = pdb;
}

// ---------------- phase 2: ef update (warp per node, uses precomputed ps/pd) ----------------
__global__ __launch_bounds__(256) void mp_phase2(const float* __restrict__ Wu1,
                                                 const float* __restrict__ Wu2)
{
  __shared__ float sU1a[2048];  // rows 0..31 of Wu1 (ef part), 32x64
  __shared__ float sW2[2048];   // 64x32
  for (int t = threadIdx.x; t < 2048; t += 256){ sU1a[t] = Wu1[t]; sW2[t] = Wu2[t]; }
  __syncthreads();
  int lane = threadIdx.x & 31;
  int i = blockIdx.x*8 + (threadIdx.x >> 5);
  if (i >= NRES) return;

  float pda = g_pd[i*64 + lane];
  float pdb = g_pd[i*64 + 32 + lane];

  #pragma unroll 2
  for (int k = 0; k < KNN; k++){
    int e = i*KNN + k;
    int s = g_src[e];
    float efc = g_ef[e*EFD + lane];
    float y0 = pda + g_ps[s*64 + lane];
    float y1 = pdb + g_ps[s*64 + 32 + lane];
    #pragma unroll
    for (int d = 0; d < 32; d++){
      float a = __shfl_sync(0xffffffffu, efc, d);
      y0 = fmaf(a, sU1a[d*64 + lane],      y0);
      y1 = fmaf(a, sU1a[d*64 + 32 + lane], y1);
    }
    y0 = fmaxf(y0, 0.f); y1 = fmaxf(y1, 0.f);
    float oA = 0.f, oB = 0.f;
    #pragma unroll
    for (int h = 0; h < 32; h++){
      oA = fmaf(__shfl_sync(0xffffffffu, y0, h), sW2[h*32 + lane],      oA);
      oB = fmaf(__shfl_sync(0xffffffffu, y1, h), sW2[(32+h)*32 + lane], oB);
    }
    g_ef[e*EFD + lane] = efc + oA + oB;
  }
}

// ---------------- decode: atoms + seq ----------------
__global__ __launch_bounds__(256) void decode_kernel(int buf,
    const float* __restrict__ rot, const float* __restrict__ trans,
    const float* __restrict__ Wp0, const float* __restrict__ Wt, const float* __restrict__ bt,
    const float* __restrict__ Wseq1, const float* __restrict__ bseq1,
    const float* __restrict__ Wseq2, const float* __restrict__ bseq2,
    const float* __restrict__ Wseq3, const float* __restrict__ bseq3,
    const float* __restrict__ lit_pos, const float* __restrict__ Wchi, const float* __restrict__ Wpsi,
    float* __restrict__ out)
{
  __shared__ float su[8][162];
  int lane = threadIdx.x & 31;
  int w = threadIdx.x >> 5;
  int i = blockIdx.x*8 + w;
  if (i >= NRES) return;

  float h0c = g_h0[buf][i*HDIM + lane];
  float t0 = 0.f;
  #pragma unroll
  for (int d = 0; d < 32; d++) t0 = fmaf(__shfl_sync(0xffffffffu, h0c, d), Wp0[d*32 + lane], t0);
  t0 = fmaxf(t0, 0.f);
  #pragma unroll
  for (int r = 0; r < 6; r++){
    int idx = r*32 + lane;
    int widx = idx < 162 ? idx : 161;
    float u = bt[widx];
    #pragma unroll
    for (int c = 0; c < 32; c++) u = fmaf(__shfl_sync(0xffffffffu, t0, c), Wt[c*162 + widx], u);
    if (idx < 162) su[w][idx] = u;
  }
  __syncwarp();
  for (int j = lane; j < 81; j += 32){
    float a = su[w][2*j], b = su[w][2*j+1];
    float ea = a + 1e-8f, eb = b + 1e-8f;
    float den = sqrtf(ea*ea + eb*eb);
    su[w][2*j]   = a / den;
    su[w][2*j+1] = b / den;
  }
  __syncwarp();
  float p0 = su[w][0], p1 = su[w][1];
  float r00=rot[i*9+0], r01=rot[i*9+1], r02=rot[i*9+2];
  float r10=rot[i*9+3], r11=rot[i*9+4], r12=rot[i*9+5];
  float r20=rot[i*9+6], r21=rot[i*9+7], r22=rot[i*9+8];

  for (int m = lane; m < 91; m += 32){
    int k, a;
    if (m < 4){ k = 0; a = m; }
    else { k = c_aa[m-4]; a = 4 + c_off[m-4]; }
    float chi[8];
    #pragma unroll
    for (int t = 0; t < 4; t++){
      chi[2*t]   = su[w][2*(1 + k*4 + t)];
      chi[2*t+1] = su[w][2*(1 + k*4 + t) + 1];
    }
    float l[3];
    #pragma unroll
    for (int j = 0; j < 3; j++){
      float acc = lit_pos[(k*14 + a)*3 + j];
      #pragma unroll
      for (int c = 0; c < 8; c++) acc = fmaf(chi[c], Wchi[(c*14 + a)*3 + j], acc);
      acc = fmaf(p0, Wpsi[(0*14 + a)*3 + j], acc);
      acc = fmaf(p1, Wpsi[(1*14 + a)*3 + j], acc);
      l[j] = acc;
    }
    out[((size_t)i*91 + m)*3 + 0] = r00*l[0] + r01*l[1] + r02*l[2];
    out[((size_t)i*91 + m)*3 + 1] = r10*l[0] + r11*l[1] + r12*l[2];
    out[((size_t)i*91 + m)*3 + 2] = r20*l[0] + r21*l[1] + r22*l[2];
  }

  float s1a = bseq1[lane], s1b = bseq1[32 + lane];
  #pragma unroll
  for (int d = 0; d < 32; d++){
    float h = __shfl_sync(0xffffffffu, h0c, d);
    s1a = fmaf(h, Wseq1[d*64 + lane],      s1a);
    s1b = fmaf(h, Wseq1[d*64 + 32 + lane], s1b);
  }
  s1a = fmaxf(s1a, 0.f); s1b = fmaxf(s1b, 0.f);
  float s2 = bseq2[lane];
  #pragma unroll
  for (int h = 0; h < 32; h++) s2 = fmaf(__shfl_sync(0xffffffffu, s1a, h), Wseq2[h*32 + lane], s2);
  #pragma unroll
  for (int h = 0; h < 32; h++) s2 = fmaf(__shfl_sync(0xffffffffu, s1b, h), Wseq2[(32+h)*32 + lane], s2);
  s2 = fmaxf(s2, 0.f);
  int ll = lane < 20 ? lane : 19;
  float lg = bseq3[ll];
  #pragma unroll
  for (int c = 0; c < 32; c++) lg = fmaf(__shfl_sync(0xffffffffu, s2, c), Wseq3[c*20 + ll], lg);
  float mv = (lane < 20) ? lg : -3.0e38f;
  #pragma unroll
  for (int o = 16; o > 0; o >>= 1) mv = fmaxf(mv, __shfl_xor_sync(0xffffffffu, mv, o));
  float ex = (lane < 20) ? expf(lg - mv) : 0.f;
  #pragma unroll
  for (int o = 16; o > 0; o >>= 1) ex += __shfl_xor_sync(0xffffffffu, ex, o);
  if (lane < 20) out[(size_t)NRES*273 + (size_t)i*20 + lane] = lg - mv - logf(ex);
}

// ---------------- launch ----------------
extern "C" void kernel_launch(void* const* d_in, const int* in_sizes, int n_in,
                              void* d_out, int out_size)
{
  const float* bb      = (const float*)d_in[0];
  const float* latent  = (const float*)d_in[1];
  const float* rrot    = (const float*)d_in[2];
  const float* rtrans  = (const float*)d_in[3];
  const float* Wemb0   = (const float*)d_in[4];
  const float* Wemb1   = (const float*)d_in[5];
  const float* We1s    = (const float*)d_in[6];
  const float* Wss     = (const float*)d_in[7];
  const float* Wds     = (const float*)d_in[8];
  const float* We2s    = (const float*)d_in[9];
  const float* Wvs     = (const float*)d_in[10];
  const float* W0s     = (const float*)d_in[11];
  const float* W1s     = (const float*)d_in[12];
  const float* Wu1s    = (const float*)d_in[13];
  const float* Wu2s    = (const float*)d_in[14];
  const float* Wp0     = (const float*)d_in[15];
  const float* Wt      = (const float*)d_in[16];
  const float* bt      = (const float*)d_in[17];
  const float* Wseq1   = (const float*)d_in[18];
  const float* bseq1   = (const float*)d_in[19];
  const float* Wseq2   = (const float*)d_in[20];
  const float* bseq2   = (const float*)d_in[21];
  const float* Wseq3   = (const float*)d_in[22];
  const float* bseq3   = (const float*)d_in[23];
  const float* lit_pos = (const float*)d_in[24];
  const float* Wchi    = (const float*)d_in[25];
  const float* Wpsi    = (const float*)d_in[26];
  const int*   bids    = (const int*)d_in[28];
  float* out = (float*)d_out;

  init_ranges_kernel<<<1, 32>>>();
  batch_range_kernel<<<(NRES+255)/256, 256>>>(bids);
  node_embed_kernel<<<1250, 256>>>(bb, latent, Wemb0, Wemb1);
  knn_kernel<<<1250, 256>>>(bids);
  edge_init_kernel<<<(NEDGE+255)/256, 256>>>();

  int cur = 0;
  for (int l = 0; l < NLAYERS; l++){
    precompA_kernel<<<1250, 256>>>(cur,
        Wss + l*HDIM*HDIM, Wds + l*HDIM*HDIM, Wvs + l*HDIM*HDIM);
    mp_phase1<<<1250, 256>>>(cur,
        We1s + l*EFD*HDIM, We2s + l*HDIM*HDIM,
        W0s + l*HDIM*HDIM, W1s + l*HDIM*HDIM,
        Wu1s + l*96*64);
    mp_phase2<<<1250, 256>>>(Wu1s + l*96*64, Wu2s + l*64*32);
    cur ^= 1;
  }

  decode_kernel<<<1250, 256>>>(cur, rrot, rtrans, Wp0, Wt, bt,
                               Wseq1, bseq1, Wseq2, bseq2, Wseq3, bseq3,
                               lit_pos, Wchi, Wpsi, out);
}

// round 4
// speedup vs baseline: 2.6420x; 1.4728x over previous
#include <cuda_runtime.h>
#include <math.h>

#define NRES 10000
#define KNN 30
#define HDIM 32
#define NLAYERS 4
#define EFD 32
#define NEDGE (NRES*KNN)

// ---------------- device scratch ----------------
__device__ float g_h0[2][NRES*HDIM];
__device__ float g_h1[2][NRES*3*HDIM];
__device__ float g_ef[NEDGE*EFD];
__device__ int   g_src[NEDGE];
__device__ float4 g_xca4[NRES];           // (x,y,z,|x|^2)
__device__ int   g_bstart[8];
__device__ int   g_bend[8];
// per-node precomputes
__device__ float g_hs[NRES*HDIM];         // h0 @ Wss
__device__ float g_hd[NRES*HDIM];         // h0 @ Wds
__device__ float g_hv[NRES*3*HDIM];       // h1 @ Wvs
__device__ float g_ps[NRES*64];           // h0new @ Wu1[32:64]
__device__ float g_pd[NRES*64];           // h0new @ Wu1[64:96]

__constant__ int c_aa[87] = {
  0,
  1,1,1,1,1,1,1, 2,2,2,2, 3,3,3,3, 4,4, 5,5,5,5,5, 6,6,6,6,6,
  8,8,8,8,8,8, 9,9,9,9, 10,10,10,10, 11,11,11,11,11, 12,12,12,12,
  13,13,13,13,13,13,13, 14,14,14, 15,15, 16,16,16,
  17,17,17,17,17,17,17,17,17,17, 18,18,18,18,18,18,18,18, 19,19,19
};
__constant__ int c_off[87] = {
  0,
  0,1,2,3,4,5,6, 0,1,2,3, 0,1,2,3, 0,1, 0,1,2,3,4, 0,1,2,3,4,
  0,1,2,3,4,5, 0,1,2,3, 0,1,2,3, 0,1,2,3,4, 0,1,2,3,
  0,1,2,3,4,5,6, 0,1,2, 0,1, 0,1,2,
  0,1,2,3,4,5,6,7,8,9, 0,1,2,3,4,5,6,7, 0,1,2
};

__device__ __forceinline__ float fin0(float v){ return isfinite(v) ? v : 0.f; }

// ---------------- batch ranges ----------------
__global__ void init_ranges_kernel(){
  int t = threadIdx.x;
  if (t < 8){ g_bstart[t] = NRES; g_bend[t] = 0; }
}
__global__ void batch_range_kernel(const int* __restrict__ bid){
  int i = blockIdx.x*blockDim.x + threadIdx.x;
  if (i >= NRES) return;
  int b = bid[i];
  atomicMin(&g_bstart[b], i);
  atomicMax(&g_bend[b], i+1);
}

// ---------------- node features + embeddings (warp per node, lane=channel) ----------------
__global__ __launch_bounds__(256) void node_embed_kernel(
    const float* __restrict__ bb, const float* __restrict__ lat,
    const float* __restrict__ Wemb0, const float* __restrict__ Wemb1)
{
  int lane = threadIdx.x & 31;
  int i = blockIdx.x*8 + (threadIdx.x >> 5);
  if (i >= NRES) return;

  float ca0 = bb[i*12+3], ca1 = bb[i*12+4], ca2 = bb[i*12+5];
  if (lane == 0){
    g_xca4[i] = make_float4(ca0, ca1, ca2, ca0*ca0 + ca1*ca1 + ca2*ca2);
  }

  float Dv[3];
  #pragma unroll
  for (int t3 = 0; t3 < 3; t3++){
    int t = 3*i + t3;
    float D = 0.f;
    if (t >= 1 && t <= 3*NRES - 3){
      int d0 = t - 1;
      float x[4][3];
      #pragma unroll
      for (int q = 0; q < 4; q++){
        int m = d0 + q; int r = m/3; int am = m - r*3;
        x[q][0] = bb[r*12 + am*3 + 0];
        x[q][1] = bb[r*12 + am*3 + 1];
        x[q][2] = bb[r*12 + am*3 + 2];
      }
      float u2[3], u1[3], u0[3];
      #pragma unroll
      for (int c = 0; c < 3; c++){ u2[c]=x[1][c]-x[0][c]; u1[c]=x[2][c]-x[1][c]; u0[c]=x[3][c]-x[2][c]; }
      float n2n = sqrtf(u2[0]*u2[0]+u2[1]*u2[1]+u2[2]*u2[2]) + 1e-8f;
      float n1n = sqrtf(u1[0]*u1[0]+u1[1]*u1[1]+u1[2]*u1[2]) + 1e-8f;
      float n0n = sqrtf(u0[0]*u0[0]+u0[1]*u0[1]+u0[2]*u0[2]) + 1e-8f;
      #pragma unroll
      for (int c = 0; c < 3; c++){ u2[c]/=n2n; u1[c]/=n1n; u0[c]/=n0n; }
      float c21[3] = { u2[1]*u1[2]-u2[2]*u1[1], u2[2]*u1[0]-u2[0]*u1[2], u2[0]*u1[1]-u2[1]*u1[0] };
      float c10[3] = { u1[1]*u0[2]-u1[2]*u0[1], u1[2]*u0[0]-u1[0]*u0[2], u1[0]*u0[1]-u1[1]*u0[0] };
      float l21 = sqrtf(c21[0]*c21[0]+c21[1]*c21[1]+c21[2]*c21[2]) + 1e-8f;
      float l10 = sqrtf(c10[0]*c10[0]+c10[1]*c10[1]+c10[2]*c10[2]) + 1e-8f;
      #pragma unroll
      for (int c = 0; c < 3; c++){ c21[c]/=l21; c10[c]/=l10; }
      float cosD = c21[0]*c10[0]+c21[1]*c10[1]+c21[2]*c10[2];
      cosD = fminf(fmaxf(cosD, -1.f + 1e-7f), 1.f - 1e-7f);
      float sdot = u2[0]*c10[0]+u2[1]*c10[1]+u2[2]*c10[2];
      float sgn = (sdot > 0.f) ? 1.f : ((sdot < 0.f) ? -1.f : 0.f);
      D = sgn * acosf(cosD);
    }
    Dv[t3] = D;
  }
  float x0[7] = { cosf(Dv[0]), cosf(Dv[1]), cosf(Dv[2]),
                  sinf(Dv[0]), sinf(Dv[1]), sinf(Dv[2]), 1.f };

  float v[7][3];
  #pragma unroll
  for (int a = 0; a < 4; a++){
    v[a][0] = bb[i*12 + a*3 + 0] - ca0;
    v[a][1] = bb[i*12 + a*3 + 1] - ca1;
    v[a][2] = bb[i*12 + a*3 + 2] - ca2;
  }
  if (i < NRES-1){
    float dx = bb[(i+1)*12+3] - ca0, dy = bb[(i+1)*12+4] - ca1, dz = bb[(i+1)*12+5] - ca2;
    float n = sqrtf(dx*dx+dy*dy+dz*dz) + 1e-8f;
    v[4][0]=dx/n; v[4][1]=dy/n; v[4][2]=dz/n;
  } else { v[4][0]=v[4][1]=v[4][2]=0.f; }
  if (i > 0){
    float dx = ca0 - bb[(i-1)*12+3], dy = ca1 - bb[(i-1)*12+4], dz = ca2 - bb[(i-1)*12+5];
    float n = sqrtf(dx*dx+dy*dy+dz*dz) + 1e-8f;
    v[5][0]=-dx/n; v[5][1]=-dy/n; v[5][2]=-dz/n;
  } else { v[5][0]=v[5][1]=v[5][2]=0.f; }
  {
    float b0 = ca0 - bb[i*12+0], b1 = ca1 - bb[i*12+1], b2 = ca2 - bb[i*12+2];
    float cc0 = bb[i*12+6] - ca0, cc1 = bb[i*12+7] - ca1, cc2 = bb[i*12+8] - ca2;
    float a0 = b1*cc2 - b2*cc1, a1 = b2*cc0 - b0*cc2, a2 = b0*cc1 - b1*cc0;
    v[6][0] = -0.58273431f*a0 + 0.56802827f*b0 - 0.54067466f*cc0;
    v[6][1] = -0.58273431f*a1 + 0.56802827f*b1 - 0.54067466f*cc1;
    v[6][2] = -0.58273431f*a2 + 0.56802827f*b2 - 0.54067466f*cc2;
  }
  #pragma unroll
  for (int q = 0; q < 7; q++){
    v[q][0]=fin0(v[q][0]); v[q][1]=fin0(v[q][1]); v[q][2]=fin0(v[q][2]);
  }

  float acc = 0.f;
  #pragma unroll
  for (int d = 0; d < 7; d++) acc = fmaf(x0[d], Wemb0[d*32 + lane], acc);
  for (int d = 0; d < 32; d++) acc = fmaf(lat[(i*4+0)*32 + d], Wemb0[(7+d)*32 + lane], acc);
  g_h0[0][i*32 + lane] = fmaxf(acc, 0.f);

  #pragma unroll
  for (int j = 0; j < 3; j++){
    float a2 = 0.f;
    #pragma unroll
    for (int d = 0; d < 7; d++) a2 = fmaf(v[d][j], Wemb1[d*32 + lane], a2);
    for (int d = 0; d < 32; d++) a2 = fmaf(lat[(i*4+1+j)*32 + d], Wemb1[(7+d)*32 + lane], a2);
    g_h1[0][(i*3+j)*32 + lane] = a2;
  }
}

// ---------------- kNN: one WARP per row, register-only bitonic top-32 ----------------
__device__ __forceinline__ unsigned long long shfx64(unsigned long long v, int m){
  return __shfl_xor_sync(0xffffffffu, v, m);
}

__global__ __launch_bounds__(256) void knn_kernel(const int* __restrict__ bid){
  int lane = threadIdx.x & 31;
  int i = blockIdx.x*8 + (threadIdx.x >> 5);
  if (i >= NRES) return;
  float4 qi = g_xca4[i];
  int b = bid[i];
  int lo = g_bstart[b], hi = g_bend[b];

  const unsigned long long INF = 0xFFFFFFFFFFFFFFFFull;
  unsigned long long state = INF;   // sorted ascending across lanes (lane 0 smallest)
  unsigned long long worst = INF;   // state at lane 31

  for (int j0 = lo; j0 < hi; j0 += 32){
    int j = j0 + lane;
    unsigned long long key = INF;
    if (j < hi && j != i){
      float4 qj = g_xca4[j];
      float d2 = fmaf(-2.f, qi.x*qj.x + qi.y*qj.y + qi.z*qj.z, qi.w + qj.w);
      unsigned int fb = __float_as_uint(d2);
      fb = (fb & 0x80000000u) ? ~fb : (fb | 0x80000000u);  // order-preserving flip
      key = ((unsigned long long)fb << 32) | (unsigned int)j;
    }
    if (!__any_sync(0xffffffffu, key < worst)) continue;

    // bitonic sort `key` ascending across lanes (15 compare-exchange stages)
    #pragma unroll
    for (int k = 2; k <= 32; k <<= 1){
      #pragma unroll
      for (int jj = k >> 1; jj > 0; jj >>= 1){
        unsigned long long o = shfx64(key, jj);
        bool up = ((lane & k) == 0);          // lane&32 == 0 always -> final ascending
        bool lower = ((lane & jj) == 0);
        bool keepmin = (up == lower);
        key = ((o < key) == keepmin) ? o : key;
      }
    }
    // reverse new (descending) and take elementwise min with ascending state:
    // lower half of the 64-element bitonic exchange = 32 smallest overall (bitonic seq)
    unsigned long long rev = shfx64(key, 31);
    unsigned long long m = (rev < state) ? rev : state;
    // bitonic merge to restore ascending order (5 stages)
    #pragma unroll
    for (int jj = 16; jj > 0; jj >>= 1){
      unsigned long long o = shfx64(m, jj);
      bool lower = ((lane & jj) == 0);
      m = ((o < m) == lower) ? o : m;
    }
    state = m;
    worst = __shfl_sync(0xffffffffu, state, 31);
  }

  if (lane < KNN){
    g_src[i*KNN + lane] = (state == INF) ? i : (int)(unsigned int)(state & 0xFFFFFFFFull);
  }
}

// ---------------- edge init: ef only ----------------
__global__ void edge_init_kernel(){
  int e = blockIdx.x*blockDim.x + threadIdx.x;
  if (e >= NEDGE) return;
  int i = e / KNN;
  int s = g_src[e];
  float4 qi = g_xca4[i], qs = g_xca4[s];
  float vx = qi.x - qs.x, vy = qi.y - qs.y, vz = qi.z - qs.z;
  float dist = sqrtf(vx*vx + vy*vy + vz*vz);
  float* ef = &g_ef[e*EFD];
  #pragma unroll
  for (int j = 0; j < 16; j++){
    float mu = (float)j * (20.f/15.f);
    float t = (dist - mu) / 1.25f;
    ef[j] = expf(-t*t);
  }
  float diff = (float)(s - i);
  #pragma unroll
  for (int f = 0; f < 8; f++){
    float fr = expf(-((float)(2*f)/16.f) * 9.210340371976184f);
    float a = diff * fr;
    ef[16+f] = cosf(a);
    ef[24+f] = sinf(a);
  }
}

// ---------------- per-node precompute: hs = h0@Wss, hd = h0@Wds, hv = h1@Wvs ----------------
__global__ __launch_bounds__(256) void precompA_kernel(int buf,
    const float* __restrict__ Wss, const float* __restrict__ Wds, const float* __restrict__ Wvs)
{
  __shared__ float sWss[1024], sWds[1024], sWvs[1024];
  for (int t = threadIdx.x; t < 1024; t += 256){ sWss[t]=Wss[t]; sWds[t]=Wds[t]; sWvs[t]=Wvs[t]; }
  __syncthreads();
  int lane = threadIdx.x & 31;
  int i = blockIdx.x*8 + (threadIdx.x >> 5);
  if (i >= NRES) return;
  float h0 = g_h0[buf][i*32 + lane];
  float hs0 = 0.f, hs1 = 0.f, hd0 = 0.f, hd1 = 0.f;
  #pragma unroll
  for (int d = 0; d < 32; d += 2){
    float a = __shfl_sync(0xffffffffu, h0, d);
    float b = __shfl_sync(0xffffffffu, h0, d+1);
    hs0 = fmaf(a, sWss[d*32+lane], hs0);     hs1 = fmaf(b, sWss[(d+1)*32+lane], hs1);
    hd0 = fmaf(a, sWds[d*32+lane], hd0);     hd1 = fmaf(b, sWds[(d+1)*32+lane], hd1);
  }
  g_hs[i*32+lane] = hs0 + hs1;
  g_hd[i*32+lane] = hd0 + hd1;
  #pragma unroll
  for (int c = 0; c < 3; c++){
    float h1 = g_h1[buf][(i*3+c)*32 + lane];
    float a0 = 0.f, a1 = 0.f;
    #pragma unroll
    for (int d = 0; d < 32; d += 2){
      a0 = fmaf(__shfl_sync(0xffffffffu, h1, d),   sWvs[d*32+lane],     a0);
      a1 = fmaf(__shfl_sync(0xffffffffu, h1, d+1), sWvs[(d+1)*32+lane], a1);
    }
    g_hv[i*96 + c*32 + lane] = a0 + a1;
  }
}

// ---------------- phase 1: edge messages + node update + fused ps/pd precompute ----------------
__global__ __launch_bounds__(256) void mp_phase1(int bufIn,
    const float* __restrict__ We1, const float* __restrict__ We2,
    const float* __restrict__ W0,  const float* __restrict__ W1,
    const float* __restrict__ Wu1)
{
  __shared__ float sWe1[1024], sWe2[1024], sW0[1024], sW1[1024];
  __shared__ float sU1b[2048], sU1c[2048];
  for (int t = threadIdx.x; t < 1024; t += 256){
    sWe1[t]=We1[t]; sWe2[t]=We2[t]; sW0[t]=W0[t]; sW1[t]=W1[t];
  }
  for (int t = threadIdx.x; t < 2048; t += 256){
    sU1b[t] = Wu1[2048 + t];
    sU1c[t] = Wu1[4096 + t];
  }
  __syncthreads();
  const float* h0in = g_h0[bufIn];  float* h0out = g_h0[bufIn^1];
  const float* h1in = g_h1[bufIn];  float* h1out = g_h1[bufIn^1];
  int lane = threadIdx.x & 31;
  int i = blockIdx.x*8 + (threadIdx.x >> 5);
  if (i >= NRES) return;

  float h0d = h0in[i*HDIM + lane];
  float hd  = g_hd[i*HDIM + lane];
  float acc0 = 0.f, av0 = 0.f, av1 = 0.f, av2 = 0.f;

  #pragma unroll 2
  for (int k = 0; k < KNN; k++){
    int e = i*KNN + k;
    int s = g_src[e];
    float efc = g_ef[e*EFD + lane];
    float t0 = hd + g_hs[s*HDIM + lane];
    float t1 = 0.f;
    #pragma unroll
    for (int d = 0; d < 32; d += 2){
      t0 = fmaf(__shfl_sync(0xffffffffu, efc, d),   sWe1[d*32+lane],     t0);
      t1 = fmaf(__shfl_sync(0xffffffffu, efc, d+1), sWe1[(d+1)*32+lane], t1);
    }
    float t = fmaxf(t0 + t1, 0.f);
    float g0 = 0.f, g1 = 0.f;
    #pragma unroll
    for (int d = 0; d < 32; d += 2){
      g0 = fmaf(__shfl_sync(0xffffffffu, t, d),   sWe2[d*32+lane],     g0);
      g1 = fmaf(__shfl_sync(0xffffffffu, t, d+1), sWe2[(d+1)*32+lane], g1);
    }
    float g = g0 + g1;
    acc0 = fmaf(g, h0in[s*HDIM + lane], acc0);
    const float* hv = &g_hv[s*96];
    av0 = fmaf(g, hv[lane],      av0);
    av1 = fmaf(g, hv[32+lane],   av1);
    av2 = fmaf(g, hv[64+lane],   av2);
  }
  const float inv = 1.f/(float)KNN;
  acc0 *= inv; av0 *= inv; av1 *= inv; av2 *= inv;

  float u0 = 0.f, u1 = 0.f;
  #pragma unroll
  for (int d = 0; d < 32; d += 2){
    u0 = fmaf(__shfl_sync(0xffffffffu, acc0, d),   sW0[d*32+lane],     u0);
    u1 = fmaf(__shfl_sync(0xffffffffu, acc0, d+1), sW0[(d+1)*32+lane], u1);
  }
  float h0new = h0d + fmaxf(u0 + u1, 0.f);
  h0out[i*HDIM + lane] = h0new;

  float o0 = 0.f, o1 = 0.f, o2 = 0.f;
  #pragma unroll
  for (int d = 0; d < 32; d++){
    float w = sW1[d*32+lane];
    o0 = fmaf(__shfl_sync(0xffffffffu, av0, d), w, o0);
    o1 = fmaf(__shfl_sync(0xffffffffu, av1, d), w, o1);
    o2 = fmaf(__shfl_sync(0xffffffffu, av2, d), w, o2);
  }
  h1out[(i*3+0)*HDIM + lane] = h1in[(i*3+0)*HDIM + lane] + o0;
  h1out[(i*3+1)*HDIM + lane] = h1in[(i*3+1)*HDIM + lane] + o1;
  h1out[(i*3+2)*HDIM + lane] = h1in[(i*3+2)*HDIM + lane] + o2;

  float psa = 0.f, psb = 0.f, pda = 0.f, pdb = 0.f;
  #pragma unroll
  for (int d = 0; d < 32; d++){
    float h = __shfl_sync(0xffffffffu, h0new, d);
    psa = fmaf(h, sU1b[d*64 + lane],      psa);
    psb = fmaf(h, sU1b[d*64 + 32 + lane], psb);
    pda = fmaf(h, sU1c[d*64 + lane],      pda);
    pdb = fmaf(h, sU1c[d*64 + 32 + lane], pdb);
  }
  g_ps[i*64 + lane]      = psa;
  g_ps[i*64 + 32 + lane] = psb;
  g_pd[i*64 + lane]      = pda;
  g_pd[i*64 + 32 + lane] = pdb;
}

// ---------------- phase 2: ef update ----------------
__global__ __launch_bounds__(256) void mp_phase2(const float* __restrict__ Wu1,
                                                 const float* __restrict__ Wu2)
{
  __shared__ float sU1a[2048];
  __shared__ float sW2[2048];
  for (int t = threadIdx.x; t < 2048; t += 256){ sU1a[t] = Wu1[t]; sW2[t] = Wu2[t]; }
  __syncthreads();
  int lane = threadIdx.x & 31;
  int i = blockIdx.x*8 + (threadIdx.x >> 5);
  if (i >= NRES) return;

  float pda = g_pd[i*64 + lane];
  float pdb = g_pd[i*64 + 32 + lane];

  #pragma unroll 2
  for (int k = 0; k < KNN; k++){
    int e = i*KNN + k;
    int s = g_src[e];
    float efc = g_ef[e*EFD + lane];
    float y0 = pda + g_ps[s*64 + lane];
    float y1 = pdb + g_ps[s*64 + 32 + lane];
    #pragma unroll
    for (int d = 0; d < 32; d++){
      float a = __shfl_sync(0xffffffffu, efc, d);
      y0 = fmaf(a, sU1a[d*64 + lane],      y0);
      y1 = fmaf(a, sU1a[d*64 + 32 + lane], y1);
    }
    y0 = fmaxf(y0, 0.f); y1 = fmaxf(y1, 0.f);
    float oA = 0.f, oB = 0.f;
    #pragma unroll
    for (int h = 0; h < 32; h++){
      oA = fmaf(__shfl_sync(0xffffffffu, y0, h), sW2[h*32 + lane],      oA);
      oB = fmaf(__shfl_sync(0xffffffffu, y1, h), sW2[(32+h)*32 + lane], oB);
    }
    g_ef[e*EFD + lane] = efc + oA + oB;
  }
}

// ---------------- decode: atoms + seq ----------------
__global__ __launch_bounds__(256) void decode_kernel(int buf,
    const float* __restrict__ rot, const float* __restrict__ trans,
    const float* __restrict__ Wp0, const float* __restrict__ Wt, const float* __restrict__ bt,
    const float* __restrict__ Wseq1, const float* __restrict__ bseq1,
    const float* __restrict__ Wseq2, const float* __restrict__ bseq2,
    const float* __restrict__ Wseq3, const float* __restrict__ bseq3,
    const float* __restrict__ lit_pos, const float* __restrict__ Wchi, const float* __restrict__ Wpsi,
    float* __restrict__ out)
{
  __shared__ float su[8][162];
  int lane = threadIdx.x & 31;
  int w = threadIdx.x >> 5;
  int i = blockIdx.x*8 + w;
  if (i >= NRES) return;

  float h0c = g_h0[buf][i*HDIM + lane];
  float t0 = 0.f;
  #pragma unroll
  for (int d = 0; d < 32; d++) t0 = fmaf(__shfl_sync(0xffffffffu, h0c, d), Wp0[d*32 + lane], t0);
  t0 = fmaxf(t0, 0.f);
  #pragma unroll
  for (int r = 0; r < 6; r++){
    int idx = r*32 + lane;
    int widx = idx < 162 ? idx : 161;
    float u = bt[widx];
    #pragma unroll
    for (int c = 0; c < 32; c++) u = fmaf(__shfl_sync(0xffffffffu, t0, c), Wt[c*162 + widx], u);
    if (idx < 162) su[w][idx] = u;
  }
  __syncwarp();
  for (int j = lane; j < 81; j += 32){
    float a = su[w][2*j], b = su[w][2*j+1];
    float ea = a + 1e-8f, eb = b + 1e-8f;
    float den = sqrtf(ea*ea + eb*eb);
    su[w][2*j]   = a / den;
    su[w][2*j+1] = b / den;
  }
  __syncwarp();
  float p0 = su[w][0], p1 = su[w][1];
  float r00=rot[i*9+0], r01=rot[i*9+1], r02=rot[i*9+2];
  float r10=rot[i*9+3], r11=rot[i*9+4], r12=rot[i*9+5];
  float r20=rot[i*9+6], r21=rot[i*9+7], r22=rot[i*9+8];

  for (int m = lane; m < 91; m += 32){
    int k, a;
    if (m < 4){ k = 0; a = m; }
    else { k = c_aa[m-4]; a = 4 + c_off[m-4]; }
    float chi[8];
    #pragma unroll
    for (int t = 0; t < 4; t++){
      chi[2*t]   = su[w][2*(1 + k*4 + t)];
      chi[2*t+1] = su[w][2*(1 + k*4 + t) + 1];
    }
    float l[3];
    #pragma unroll
    for (int j = 0; j < 3; j++){
      float acc = lit_pos[(k*14 + a)*3 + j];
      #pragma unroll
      for (int c = 0; c < 8; c++) acc = fmaf(chi[c], Wchi[(c*14 + a)*3 + j], acc);
      acc = fmaf(p0, Wpsi[(0*14 + a)*3 + j], acc);
      acc = fmaf(p1, Wpsi[(1*14 + a)*3 + j], acc);
      l[j] = acc;
    }
    out[((size_t)i*91 + m)*3 + 0] = r00*l[0] + r01*l[1] + r02*l[2];
    out[((size_t)i*91 + m)*3 + 1] = r10*l[0] + r11*l[1] + r12*l[2];
    out[((size_t)i*91 + m)*3 + 2] = r20*l[0] + r21*l[1] + r22*l[2];
  }

  float s1a = bseq1[lane], s1b = bseq1[32 + lane];
  #pragma unroll
  for (int d = 0; d < 32; d++){
    float h = __shfl_sync(0xffffffffu, h0c, d);
    s1a = fmaf(h, Wseq1[d*64 + lane],      s1a);
    s1b = fmaf(h, Wseq1[d*64 + 32 + lane], s1b);
  }
  s1a = fmaxf(s1a, 0.f); s1b = fmaxf(s1b, 0.f);
  float s2 = bseq2[lane];
  #pragma unroll
  for (int h = 0; h < 32; h++) s2 = fmaf(__shfl_sync(0xffffffffu, s1a, h), Wseq2[h*32 + lane], s2);
  #pragma unroll
  for (int h = 0; h < 32; h++) s2 = fmaf(__shfl_sync(0xffffffffu, s1b, h), Wseq2[(32+h)*32 + lane], s2);
  s2 = fmaxf(s2, 0.f);
  int ll = lane < 20 ? lane : 19;
  float lg = bseq3[ll];
  #pragma unroll
  for (int c = 0; c < 32; c++) lg = fmaf(__shfl_sync(0xffffffffu, s2, c), Wseq3[c*20 + ll], lg);
  float mv = (lane < 20) ? lg : -3.0e38f;
  #pragma unroll
  for (int o = 16; o > 0; o >>= 1) mv = fmaxf(mv, __shfl_xor_sync(0xffffffffu, mv, o));
  float ex = (lane < 20) ? expf(lg - mv) : 0.f;
  #pragma unroll
  for (int o = 16; o > 0; o >>= 1) ex += __shfl_xor_sync(0xffffffffu, ex, o);
  if (lane < 20) out[(size_t)NRES*273 + (size_t)i*20 + lane] = lg - mv - logf(ex);
}

// ---------------- launch ----------------
extern "C" void kernel_launch(void* const* d_in, const int* in_sizes, int n_in,
                              void* d_out, int out_size)
{
  const float* bb      = (const float*)d_in[0];
  const float* latent  = (const float*)d_in[1];
  const float* rrot    = (const float*)d_in[2];
  const float* rtrans  = (const float*)d_in[3];
  const float* Wemb0   = (const float*)d_in[4];
  const float* Wemb1   = (const float*)d_in[5];
  const float* We1s    = (const float*)d_in[6];
  const float* Wss     = (const float*)d_in[7];
  const float* Wds     = (const float*)d_in[8];
  const float* We2s    = (const float*)d_in[9];
  const float* Wvs     = (const float*)d_in[10];
  const float* W0s     = (const float*)d_in[11];
  const float* W1s     = (const float*)d_in[12];
  const float* Wu1s    = (const float*)d_in[13];
  const float* Wu2s    = (const float*)d_in[14];
  const float* Wp0     = (const float*)d_in[15];
  const float* Wt      = (const float*)d_in[16];
  const float* bt      = (const float*)d_in[17];
  const float* Wseq1   = (const float*)d_in[18];
  const float* bseq1   = (const float*)d_in[19];
  const float* Wseq2   = (const float*)d_in[20];
  const float* bseq2   = (const float*)d_in[21];
  const float* Wseq3   = (const float*)d_in[22];
  const float* bseq3   = (const float*)d_in[23];
  const float* lit_pos = (const float*)d_in[24];
  const float* Wchi    = (const float*)d_in[25];
  const float* Wpsi    = (const float*)d_in[26];
  const int*   bids    = (const int*)d_in[28];
  float* out = (float*)d_out;

  init_ranges_kernel<<<1, 32>>>();
  batch_range_kernel<<<(NRES+255)/256, 256>>>(bids);
  node_embed_kernel<<<1250, 256>>>(bb, latent, Wemb0, Wemb1);
  knn_kernel<<<1250, 256>>>(bids);
  edge_init_kernel<<<(NEDGE+255)/256, 256>>>();

  int cur = 0;
  for (int l = 0; l < NLAYERS; l++){
    precompA_kernel<<<1250, 256>>>(cur,
        Wss + l*HDIM*HDIM, Wds + l*HDIM*HDIM, Wvs + l*HDIM*HDIM);
    mp_phase1<<<1250, 256>>>(cur,
        We1s + l*EFD*HDIM, We2s + l*HDIM*HDIM,
        W0s + l*HDIM*HDIM, W1s + l*HDIM*HDIM,
        Wu1s + l*96*64);
    mp_phase2<<<1250, 256>>>(Wu1s + l*96*64, Wu2s + l*64*32);
    cur ^= 1;
  }

  decode_kernel<<<1250, 256>>>(cur, rrot, rtrans, Wp0, Wt, bt,
                               Wseq1, bseq1, Wseq2, bseq2, Wseq3, bseq3,
                               lit_pos, Wchi, Wpsi, out);
}

// round 5
// speedup vs baseline: 2.6890x; 1.0178x over previous
#include <cuda_runtime.h>
#include <math.h>

#define NRES 10000
#define KNN 30
#define HDIM 32
#define NLAYERS 4
#define EFD 32
#define NEDGE (NRES*KNN)

// ---------------- device scratch ----------------
__device__ float g_h0[2][NRES*HDIM];
__device__ float g_h1[2][NRES*3*HDIM];
__device__ float g_ef[NEDGE*EFD];
__device__ int   g_src[NEDGE];
__device__ float4 g_xca4[NRES];           // (x,y,z,|x|^2)
__device__ int   g_bstart[8];
__device__ int   g_bend[8];
// per-node precomputes
__device__ float g_hs[NRES*HDIM];         // h0 @ Wss
__device__ float g_hd[NRES*HDIM];         // h0 @ Wds
__device__ float g_hv[NRES*3*HDIM];       // h1 @ Wvs
__device__ float g_ps[NRES*64];           // h0new @ Wu1[32:64]
__device__ float g_pd[NRES*64];           // h0new @ Wu1[64:96]

__constant__ int c_aa[87] = {
  0,
  1,1,1,1,1,1,1, 2,2,2,2, 3,3,3,3, 4,4, 5,5,5,5,5, 6,6,6,6,6,
  8,8,8,8,8,8, 9,9,9,9, 10,10,10,10, 11,11,11,11,11, 12,12,12,12,
  13,13,13,13,13,13,13, 14,14,14, 15,15, 16,16,16,
  17,17,17,17,17,17,17,17,17,17, 18,18,18,18,18,18,18,18, 19,19,19
};
__constant__ int c_off[87] = {
  0,
  0,1,2,3,4,5,6, 0,1,2,3, 0,1,2,3, 0,1, 0,1,2,3,4, 0,1,2,3,4,
  0,1,2,3,4,5, 0,1,2,3, 0,1,2,3, 0,1,2,3,4, 0,1,2,3,
  0,1,2,3,4,5,6, 0,1,2, 0,1, 0,1,2,
  0,1,2,3,4,5,6,7,8,9, 0,1,2,3,4,5,6,7, 0,1,2
};

__device__ __forceinline__ float fin0(float v){ return isfinite(v) ? v : 0.f; }

// ---------------- batch ranges ----------------
__global__ void init_ranges_kernel(){
  int t = threadIdx.x;
  if (t < 8){ g_bstart[t] = NRES; g_bend[t] = 0; }
}
__global__ void batch_range_kernel(const int* __restrict__ bid){
  int i = blockIdx.x*blockDim.x + threadIdx.x;
  if (i >= NRES) return;
  int b = bid[i];
  atomicMin(&g_bstart[b], i);
  atomicMax(&g_bend[b], i+1);
}

// ---------------- node features + embeddings (warp per node, lane=channel) ----------------
__global__ __launch_bounds__(256) void node_embed_kernel(
    const float* __restrict__ bb, const float* __restrict__ lat,
    const float* __restrict__ Wemb0, const float* __restrict__ Wemb1)
{
  int lane = threadIdx.x & 31;
  int i = blockIdx.x*8 + (threadIdx.x >> 5);
  if (i >= NRES) return;

  float ca0 = bb[i*12+3], ca1 = bb[i*12+4], ca2 = bb[i*12+5];
  if (lane == 0){
    g_xca4[i] = make_float4(ca0, ca1, ca2, ca0*ca0 + ca1*ca1 + ca2*ca2);
  }

  float Dv[3];
  #pragma unroll
  for (int t3 = 0; t3 < 3; t3++){
    int t = 3*i + t3;
    float D = 0.f;
    if (t >= 1 && t <= 3*NRES - 3){
      int d0 = t - 1;
      float x[4][3];
      #pragma unroll
      for (int q = 0; q < 4; q++){
        int m = d0 + q; int r = m/3; int am = m - r*3;
        x[q][0] = bb[r*12 + am*3 + 0];
        x[q][1] = bb[r*12 + am*3 + 1];
        x[q][2] = bb[r*12 + am*3 + 2];
      }
      float u2[3], u1[3], u0[3];
      #pragma unroll
      for (int c = 0; c < 3; c++){ u2[c]=x[1][c]-x[0][c]; u1[c]=x[2][c]-x[1][c]; u0[c]=x[3][c]-x[2][c]; }
      float n2n = sqrtf(u2[0]*u2[0]+u2[1]*u2[1]+u2[2]*u2[2]) + 1e-8f;
      float n1n = sqrtf(u1[0]*u1[0]+u1[1]*u1[1]+u1[2]*u1[2]) + 1e-8f;
      float n0n = sqrtf(u0[0]*u0[0]+u0[1]*u0[1]+u0[2]*u0[2]) + 1e-8f;
      #pragma unroll
      for (int c = 0; c < 3; c++){ u2[c]/=n2n; u1[c]/=n1n; u0[c]/=n0n; }
      float c21[3] = { u2[1]*u1[2]-u2[2]*u1[1], u2[2]*u1[0]-u2[0]*u1[2], u2[0]*u1[1]-u2[1]*u1[0] };
      float c10[3] = { u1[1]*u0[2]-u1[2]*u0[1], u1[2]*u0[0]-u1[0]*u0[2], u1[0]*u0[1]-u1[1]*u0[0] };
      float l21 = sqrtf(c21[0]*c21[0]+c21[1]*c21[1]+c21[2]*c21[2]) + 1e-8f;
      float l10 = sqrtf(c10[0]*c10[0]+c10[1]*c10[1]+c10[2]*c10[2]) + 1e-8f;
      #pragma unroll
      for (int c = 0; c < 3; c++){ c21[c]/=l21; c10[c]/=l10; }
      float cosD = c21[0]*c10[0]+c21[1]*c10[1]+c21[2]*c10[2];
      cosD = fminf(fmaxf(cosD, -1.f + 1e-7f), 1.f - 1e-7f);
      float sdot = u2[0]*c10[0]+u2[1]*c10[1]+u2[2]*c10[2];
      float sgn = (sdot > 0.f) ? 1.f : ((sdot < 0.f) ? -1.f : 0.f);
      D = sgn * acosf(cosD);
    }
    Dv[t3] = D;
  }
  float x0[7] = { cosf(Dv[0]), cosf(Dv[1]), cosf(Dv[2]),
                  sinf(Dv[0]), sinf(Dv[1]), sinf(Dv[2]), 1.f };

  float v[7][3];
  #pragma unroll
  for (int a = 0; a < 4; a++){
    v[a][0] = bb[i*12 + a*3 + 0] - ca0;
    v[a][1] = bb[i*12 + a*3 + 1] - ca1;
    v[a][2] = bb[i*12 + a*3 + 2] - ca2;
  }
  if (i < NRES-1){
    float dx = bb[(i+1)*12+3] - ca0, dy = bb[(i+1)*12+4] - ca1, dz = bb[(i+1)*12+5] - ca2;
    float n = sqrtf(dx*dx+dy*dy+dz*dz) + 1e-8f;
    v[4][0]=dx/n; v[4][1]=dy/n; v[4][2]=dz/n;
  } else { v[4][0]=v[4][1]=v[4][2]=0.f; }
  if (i > 0){
    float dx = ca0 - bb[(i-1)*12+3], dy = ca1 - bb[(i-1)*12+4], dz = ca2 - bb[(i-1)*12+5];
    float n = sqrtf(dx*dx+dy*dy+dz*dz) + 1e-8f;
    v[5][0]=-dx/n; v[5][1]=-dy/n; v[5][2]=-dz/n;
  } else { v[5][0]=v[5][1]=v[5][2]=0.f; }
  {
    float b0 = ca0 - bb[i*12+0], b1 = ca1 - bb[i*12+1], b2 = ca2 - bb[i*12+2];
    float cc0 = bb[i*12+6] - ca0, cc1 = bb[i*12+7] - ca1, cc2 = bb[i*12+8] - ca2;
    float a0 = b1*cc2 - b2*cc1, a1 = b2*cc0 - b0*cc2, a2 = b0*cc1 - b1*cc0;
    v[6][0] = -0.58273431f*a0 + 0.56802827f*b0 - 0.54067466f*cc0;
    v[6][1] = -0.58273431f*a1 + 0.56802827f*b1 - 0.54067466f*cc1;
    v[6][2] = -0.58273431f*a2 + 0.56802827f*b2 - 0.54067466f*cc2;
  }
  #pragma unroll
  for (int q = 0; q < 7; q++){
    v[q][0]=fin0(v[q][0]); v[q][1]=fin0(v[q][1]); v[q][2]=fin0(v[q][2]);
  }

  float acc = 0.f;
  #pragma unroll
  for (int d = 0; d < 7; d++) acc = fmaf(x0[d], Wemb0[d*32 + lane], acc);
  for (int d = 0; d < 32; d++) acc = fmaf(lat[(i*4+0)*32 + d], Wemb0[(7+d)*32 + lane], acc);
  g_h0[0][i*32 + lane] = fmaxf(acc, 0.f);

  #pragma unroll
  for (int j = 0; j < 3; j++){
    float a2 = 0.f;
    #pragma unroll
    for (int d = 0; d < 7; d++) a2 = fmaf(v[d][j], Wemb1[d*32 + lane], a2);
    for (int d = 0; d < 32; d++) a2 = fmaf(lat[(i*4+1+j)*32 + d], Wemb1[(7+d)*32 + lane], a2);
    g_h1[0][(i*3+j)*32 + lane] = a2;
  }
}

// ---------------- kNN: one WARP per row, register-only bitonic top-32 ----------------
__device__ __forceinline__ unsigned long long shfx64(unsigned long long v, int m){
  return __shfl_xor_sync(0xffffffffu, v, m);
}

__global__ __launch_bounds__(256) void knn_kernel(const int* __restrict__ bid){
  int lane = threadIdx.x & 31;
  int i = blockIdx.x*8 + (threadIdx.x >> 5);
  if (i >= NRES) return;
  float4 qi = g_xca4[i];
  int b = bid[i];
  int lo = g_bstart[b], hi = g_bend[b];

  const unsigned long long INF = 0xFFFFFFFFFFFFFFFFull;
  unsigned long long state = INF;
  unsigned long long worst = INF;

  for (int j0 = lo; j0 < hi; j0 += 32){
    int j = j0 + lane;
    unsigned long long key = INF;
    if (j < hi && j != i){
      float4 qj = g_xca4[j];
      float d2 = fmaf(-2.f, qi.x*qj.x + qi.y*qj.y + qi.z*qj.z, qi.w + qj.w);
      unsigned int fb = __float_as_uint(d2);
      fb = (fb & 0x80000000u) ? ~fb : (fb | 0x80000000u);
      key = ((unsigned long long)fb << 32) | (unsigned int)j;
    }
    if (!__any_sync(0xffffffffu, key < worst)) continue;

    #pragma unroll
    for (int k = 2; k <= 32; k <<= 1){
      #pragma unroll
      for (int jj = k >> 1; jj > 0; jj >>= 1){
        unsigned long long o = shfx64(key, jj);
        bool up = ((lane & k) == 0);
        bool lower = ((lane & jj) == 0);
        bool keepmin = (up == lower);
        key = ((o < key) == keepmin) ? o : key;
      }
    }
    unsigned long long rev = shfx64(key, 31);
    unsigned long long m = (rev < state) ? rev : state;
    #pragma unroll
    for (int jj = 16; jj > 0; jj >>= 1){
      unsigned long long o = shfx64(m, jj);
      bool lower = ((lane & jj) == 0);
      m = ((o < m) == lower) ? o : m;
    }
    state = m;
    worst = __shfl_sync(0xffffffffu, state, 31);
  }

  if (lane < KNN){
    g_src[i*KNN + lane] = (state == INF) ? i : (int)(unsigned int)(state & 0xFFFFFFFFull);
  }
}

// ---------------- edge init: ef only ----------------
__global__ void edge_init_kernel(){
  int e = blockIdx.x*blockDim.x + threadIdx.x;
  if (e >= NEDGE) return;
  int i = e / KNN;
  int s = g_src[e];
  float4 qi = g_xca4[i], qs = g_xca4[s];
  float vx = qi.x - qs.x, vy = qi.y - qs.y, vz = qi.z - qs.z;
  float dist = sqrtf(vx*vx + vy*vy + vz*vz);
  float* ef = &g_ef[e*EFD];
  #pragma unroll
  for (int j = 0; j < 16; j++){
    float mu = (float)j * (20.f/15.f);
    float t = (dist - mu) / 1.25f;
    ef[j] = expf(-t*t);
  }
  float diff = (float)(s - i);
  #pragma unroll
  for (int f = 0; f < 8; f++){
    float fr = expf(-((float)(2*f)/16.f) * 9.210340371976184f);
    float a = diff * fr;
    ef[16+f] = cosf(a);
    ef[24+f] = sinf(a);
  }
}

// ---------------- per-node precompute: hs = h0@Wss, hd = h0@Wds, hv = h1@Wvs ----------------
__global__ __launch_bounds__(256) void precompA_kernel(int buf,
    const float* __restrict__ Wss, const float* __restrict__ Wds, const float* __restrict__ Wvs)
{
  __shared__ float sWss[1024], sWds[1024], sWvs[1024];
  for (int t = threadIdx.x; t < 1024; t += 256){ sWss[t]=Wss[t]; sWds[t]=Wds[t]; sWvs[t]=Wvs[t]; }
  __syncthreads();
  int lane = threadIdx.x & 31;
  int i = blockIdx.x*8 + (threadIdx.x >> 5);
  if (i >= NRES) return;
  float h0 = g_h0[buf][i*32 + lane];
  float hs0 = 0.f, hs1 = 0.f, hd0 = 0.f, hd1 = 0.f;
  #pragma unroll
  for (int d = 0; d < 32; d += 2){
    float a = __shfl_sync(0xffffffffu, h0, d);
    float b = __shfl_sync(0xffffffffu, h0, d+1);
    hs0 = fmaf(a, sWss[d*32+lane], hs0);     hs1 = fmaf(b, sWss[(d+1)*32+lane], hs1);
    hd0 = fmaf(a, sWds[d*32+lane], hd0);     hd1 = fmaf(b, sWds[(d+1)*32+lane], hd1);
  }
  g_hs[i*32+lane] = hs0 + hs1;
  g_hd[i*32+lane] = hd0 + hd1;
  #pragma unroll
  for (int c = 0; c < 3; c++){
    float h1 = g_h1[buf][(i*3+c)*32 + lane];
    float a0 = 0.f, a1 = 0.f;
    #pragma unroll
    for (int d = 0; d < 32; d += 2){
      a0 = fmaf(__shfl_sync(0xffffffffu, h1, d),   sWvs[d*32+lane],     a0);
      a1 = fmaf(__shfl_sync(0xffffffffu, h1, d+1), sWvs[(d+1)*32+lane], a1);
    }
    g_hv[i*96 + c*32 + lane] = a0 + a1;
  }
}

// ---------------- phase 1: chunked two-phase GEMV, LDS.128 weights + uniform LDS.128 acts ----------------
#define CHK 10
__global__ __launch_bounds__(256) void mp_phase1(int bufIn,
    const float* __restrict__ We1, const float* __restrict__ We2,
    const float* __restrict__ W0,  const float* __restrict__ W1,
    const float* __restrict__ Wu1)
{
  __shared__ __align__(16) float sWe1T[1024];  // [c][d]
  __shared__ __align__(16) float sWe2T[1024];  // [c][d]
  __shared__ __align__(16) float sE[8][CHK][32];
  __shared__ __align__(16) float sT[8][CHK][32];
  __shared__ int sSrc[8][32];

  for (int t = threadIdx.x; t < 1024; t += 256){
    sWe1T[t] = We1[(t&31)*32 + (t>>5)];
    sWe2T[t] = We2[(t&31)*32 + (t>>5)];
  }
  __syncthreads();

  const float* h0in = g_h0[bufIn];  float* h0out = g_h0[bufIn^1];
  const float* h1in = g_h1[bufIn];  float* h1out = g_h1[bufIn^1];
  int lane = threadIdx.x & 31;
  int w = threadIdx.x >> 5;
  int i = blockIdx.x*8 + w;
  if (i >= NRES) return;

  if (lane < KNN) sSrc[w][lane] = g_src[i*KNN + lane];
  __syncwarp();

  float h0d = h0in[i*HDIM + lane];
  float hd  = g_hd[i*HDIM + lane];
  float acc0 = 0.f, av0 = 0.f, av1 = 0.f, av2 = 0.f;

  for (int c0 = 0; c0 < KNN; c0 += CHK){
    // preload ef chunk
    #pragma unroll
    for (int k = 0; k < CHK; k++)
      sE[w][k][lane] = g_ef[((size_t)(i*KNN + c0 + k))*EFD + lane];
    __syncwarp();
    // phase A: t_k = relu(hd + hs[s] + ef_k @ We1)
    #pragma unroll
    for (int k = 0; k < CHK; k++){
      int s = sSrc[w][c0 + k];
      float t0 = hd + g_hs[s*HDIM + lane];
      float t1 = 0.f;
      #pragma unroll
      for (int d4 = 0; d4 < 8; d4++){
        float4 a  = *(const float4*)&sE[w][k][d4*4];
        float4 wv = *(const float4*)&sWe1T[lane*32 + d4*4];
        t0 = fmaf(a.x, wv.x, t0); t1 = fmaf(a.y, wv.y, t1);
        t0 = fmaf(a.z, wv.z, t0); t1 = fmaf(a.w, wv.w, t1);
      }
      sT[w][k][lane] = fmaxf(t0 + t1, 0.f);
    }
    __syncwarp();
    // phase B: g_k = t_k @ We2; accumulate messages
    #pragma unroll
    for (int k = 0; k < CHK; k++){
      int s = sSrc[w][c0 + k];
      float g0 = 0.f, g1 = 0.f;
      #pragma unroll
      for (int d4 = 0; d4 < 8; d4++){
        float4 a  = *(const float4*)&sT[w][k][d4*4];
        float4 wv = *(const float4*)&sWe2T[lane*32 + d4*4];
        g0 = fmaf(a.x, wv.x, g0); g1 = fmaf(a.y, wv.y, g1);
        g0 = fmaf(a.z, wv.z, g0); g1 = fmaf(a.w, wv.w, g1);
      }
      float g = g0 + g1;
      acc0 = fmaf(g, h0in[s*HDIM + lane], acc0);
      const float* hv = &g_hv[s*96];
      av0 = fmaf(g, hv[lane],    av0);
      av1 = fmaf(g, hv[32+lane], av1);
      av2 = fmaf(g, hv[64+lane], av2);
    }
    __syncwarp();
  }

  const float inv = 1.f/(float)KNN;
  acc0 *= inv; av0 *= inv; av1 *= inv; av2 *= inv;

  // h0 update (weights via __ldg; once per node)
  float u0 = 0.f, u1 = 0.f;
  #pragma unroll
  for (int d = 0; d < 32; d += 2){
    u0 = fmaf(__shfl_sync(0xffffffffu, acc0, d),   __ldg(&W0[d*32+lane]),     u0);
    u1 = fmaf(__shfl_sync(0xffffffffu, acc0, d+1), __ldg(&W0[(d+1)*32+lane]), u1);
  }
  float h0new = h0d + fmaxf(u0 + u1, 0.f);
  h0out[i*HDIM + lane] = h0new;

  // h1 update
  float o0 = 0.f, o1 = 0.f, o2 = 0.f;
  #pragma unroll
  for (int d = 0; d < 32; d++){
    float wv = __ldg(&W1[d*32+lane]);
    o0 = fmaf(__shfl_sync(0xffffffffu, av0, d), wv, o0);
    o1 = fmaf(__shfl_sync(0xffffffffu, av1, d), wv, o1);
    o2 = fmaf(__shfl_sync(0xffffffffu, av2, d), wv, o2);
  }
  h1out[(i*3+0)*HDIM + lane] = h1in[(i*3+0)*HDIM + lane] + o0;
  h1out[(i*3+1)*HDIM + lane] = h1in[(i*3+1)*HDIM + lane] + o1;
  h1out[(i*3+2)*HDIM + lane] = h1in[(i*3+2)*HDIM + lane] + o2;

  // fused phase-2 precompute from h0new: ps = h0new@Wu1[32:64], pd = h0new@Wu1[64:96]
  const float* U1b = Wu1 + 2048;
  const float* U1c = Wu1 + 4096;
  float psa = 0.f, psb = 0.f, pda = 0.f, pdb = 0.f;
  #pragma unroll
  for (int d = 0; d < 32; d++){
    float h = __shfl_sync(0xffffffffu, h0new, d);
    psa = fmaf(h, __ldg(&U1b[d*64 + lane]),      psa);
    psb = fmaf(h, __ldg(&U1b[d*64 + 32 + lane]), psb);
    pda = fmaf(h, __ldg(&U1c[d*64 + lane]),      pda);
    pdb = fmaf(h, __ldg(&U1c[d*64 + 32 + lane]), pdb);
  }
  g_ps[i*64 + lane]      = psa;
  g_ps[i*64 + 32 + lane] = psb;
  g_pd[i*64 + lane]      = pda;
  g_pd[i*64 + 32 + lane] = pdb;
}

// ---------------- phase 2: ef update, chunked two-phase ----------------
__global__ __launch_bounds__(256) void mp_phase2(const float* __restrict__ Wu1,
                                                 const float* __restrict__ Wu2)
{
  __shared__ __align__(16) float sU1aT[2048];   // [c][d], c in 0..63
  __shared__ __align__(16) float sW2T[2048];    // [c][h], c in 0..31, h in 0..63
  __shared__ __align__(16) float sE[8][CHK][32];
  __shared__ __align__(16) float sY[8][CHK][64];
  __shared__ int sSrc[8][32];

  for (int t = threadIdx.x; t < 2048; t += 256){
    sU1aT[t] = Wu1[(t&31)*64 + (t>>5)];
    sW2T[t]  = Wu2[(t&63)*32 + (t>>6)];
  }
  __syncthreads();

  int lane = threadIdx.x & 31;
  int w = threadIdx.x >> 5;
  int i = blockIdx.x*8 + w;
  if (i >= NRES) return;

  if (lane < KNN) sSrc[w][lane] = g_src[i*KNN + lane];
  __syncwarp();

  float pda = g_pd[i*64 + lane];
  float pdb = g_pd[i*64 + 32 + lane];

  for (int c0 = 0; c0 < KNN; c0 += CHK){
    #pragma unroll
    for (int k = 0; k < CHK; k++)
      sE[w][k][lane] = g_ef[((size_t)(i*KNN + c0 + k))*EFD + lane];
    __syncwarp();
    // phase A: y_k = relu(pd + ps[s] + ef_k @ U1a)   (64-wide, 2 channels per lane)
    #pragma unroll
    for (int k = 0; k < CHK; k++){
      int s = sSrc[w][c0 + k];
      float y0 = pda + g_ps[s*64 + lane];
      float y1 = pdb + g_ps[s*64 + 32 + lane];
      #pragma unroll
      for (int d4 = 0; d4 < 8; d4++){
        float4 a  = *(const float4*)&sE[w][k][d4*4];
        float4 w0 = *(const float4*)&sU1aT[lane*32 + d4*4];
        float4 w1 = *(const float4*)&sU1aT[(lane+32)*32 + d4*4];
        y0 = fmaf(a.x, w0.x, y0); y0 = fmaf(a.y, w0.y, y0);
        y0 = fmaf(a.z, w0.z, y0); y0 = fmaf(a.w, w0.w, y0);
        y1 = fmaf(a.x, w1.x, y1); y1 = fmaf(a.y, w1.y, y1);
        y1 = fmaf(a.z, w1.z, y1); y1 = fmaf(a.w, w1.w, y1);
      }
      sY[w][k][lane]      = fmaxf(y0, 0.f);
      sY[w][k][32 + lane] = fmaxf(y1, 0.f);
    }
    __syncwarp();
    // phase B: o_k = y_k @ Wu2; ef += o
    #pragma unroll
    for (int k = 0; k < CHK; k++){
      float oA = 0.f, oB = 0.f;
      #pragma unroll
      for (int h4 = 0; h4 < 16; h4++){
        float4 a  = *(const float4*)&sY[w][k][h4*4];
        float4 wv = *(const float4*)&sW2T[lane*64 + h4*4];
        oA = fmaf(a.x, wv.x, oA); oB = fmaf(a.y, wv.y, oB);
        oA = fmaf(a.z, wv.z, oA); oB = fmaf(a.w, wv.w, oB);
      }
      g_ef[((size_t)(i*KNN + c0 + k))*EFD + lane] = sE[w][k][lane] + oA + oB;
    }
    __syncwarp();
  }
}

// ---------------- decode: atoms + seq ----------------
__global__ __launch_bounds__(256) void decode_kernel(int buf,
    const float* __restrict__ rot, const float* __restrict__ trans,
    const float* __restrict__ Wp0, const float* __restrict__ Wt, const float* __restrict__ bt,
    const float* __restrict__ Wseq1, const float* __restrict__ bseq1,
    const float* __restrict__ Wseq2, const float* __restrict__ bseq2,
    const float* __restrict__ Wseq3, const float* __restrict__ bseq3,
    const float* __restrict__ lit_pos, const float* __restrict__ Wchi, const float* __restrict__ Wpsi,
    float* __restrict__ out)
{
  __shared__ float su[8][162];
  int lane = threadIdx.x & 31;
  int w = threadIdx.x >> 5;
  int i = blockIdx.x*8 + w;
  if (i >= NRES) return;

  float h0c = g_h0[buf][i*HDIM + lane];
  float t0 = 0.f;
  #pragma unroll
  for (int d = 0; d < 32; d++) t0 = fmaf(__shfl_sync(0xffffffffu, h0c, d), Wp0[d*32 + lane], t0);
  t0 = fmaxf(t0, 0.f);
  #pragma unroll
  for (int r = 0; r < 6; r++){
    int idx = r*32 + lane;
    int widx = idx < 162 ? idx : 161;
    float u = bt[widx];
    #pragma unroll
    for (int c = 0; c < 32; c++) u = fmaf(__shfl_sync(0xffffffffu, t0, c), Wt[c*162 + widx], u);
    if (idx < 162) su[w][idx] = u;
  }
  __syncwarp();
  for (int j = lane; j < 81; j += 32){
    float a = su[w][2*j], b = su[w][2*j+1];
    float ea = a + 1e-8f, eb = b + 1e-8f;
    float den = sqrtf(ea*ea + eb*eb);
    su[w][2*j]   = a / den;
    su[w][2*j+1] = b / den;
  }
  __syncwarp();
  float p0 = su[w][0], p1 = su[w][1];
  float r00=rot[i*9+0], r01=rot[i*9+1], r02=rot[i*9+2];
  float r10=rot[i*9+3], r11=rot[i*9+4], r12=rot[i*9+5];
  float r20=rot[i*9+6], r21=rot[i*9+7], r22=rot[i*9+8];

  for (int m = lane; m < 91; m += 32){
    int k, a;
    if (m < 4){ k = 0; a = m; }
    else { k = c_aa[m-4]; a = 4 + c_off[m-4]; }
    float chi[8];
    #pragma unroll
    for (int t = 0; t < 4; t++){
      chi[2*t]   = su[w][2*(1 + k*4 + t)];
      chi[2*t+1] = su[w][2*(1 + k*4 + t) + 1];
    }
    float l[3];
    #pragma unroll
    for (int j = 0; j < 3; j++){
      float acc = lit_pos[(k*14 + a)*3 + j];
      #pragma unroll
      for (int c = 0; c < 8; c++) acc = fmaf(chi[c], Wchi[(c*14 + a)*3 + j], acc);
      acc = fmaf(p0, Wpsi[(0*14 + a)*3 + j], acc);
      acc = fmaf(p1, Wpsi[(1*14 + a)*3 + j], acc);
      l[j] = acc;
    }
    out[((size_t)i*91 + m)*3 + 0] = r00*l[0] + r01*l[1] + r02*l[2];
    out[((size_t)i*91 + m)*3 + 1] = r10*l[0] + r11*l[1] + r12*l[2];
    out[((size_t)i*91 + m)*3 + 2] = r20*l[0] + r21*l[1] + r22*l[2];
  }

  float s1a = bseq1[lane], s1b = bseq1[32 + lane];
  #pragma unroll
  for (int d = 0; d < 32; d++){
    float h = __shfl_sync(0xffffffffu, h0c, d);
    s1a = fmaf(h, Wseq1[d*64 + lane],      s1a);
    s1b = fmaf(h, Wseq1[d*64 + 32 + lane], s1b);
  }
  s1a = fmaxf(s1a, 0.f); s1b = fmaxf(s1b, 0.f);
  float s2 = bseq2[lane];
  #pragma unroll
  for (int h = 0; h < 32; h++) s2 = fmaf(__shfl_sync(0xffffffffu, s1a, h), Wseq2[h*32 + lane], s2);
  #pragma unroll
  for (int h = 0; h < 32; h++) s2 = fmaf(__shfl_sync(0xffffffffu, s1b, h), Wseq2[(32+h)*32 + lane], s2);
  s2 = fmaxf(s2, 0.f);
  int ll = lane < 20 ? lane : 19;
  float lg = bseq3[ll];
  #pragma unroll
  for (int c = 0; c < 32; c++) lg = fmaf(__shfl_sync(0xffffffffu, s2, c), Wseq3[c*20 + ll], lg);
  float mv = (lane < 20) ? lg : -3.0e38f;
  #pragma unroll
  for (int o = 16; o > 0; o >>= 1) mv = fmaxf(mv, __shfl_xor_sync(0xffffffffu, mv, o));
  float ex = (lane < 20) ? expf(lg - mv) : 0.f;
  #pragma unroll
  for (int o = 16; o > 0; o >>= 1) ex += __shfl_xor_sync(0xffffffffu, ex, o);
  if (lane < 20) out[(size_t)NRES*273 + (size_t)i*20 + lane] = lg - mv - logf(ex);
}

// ---------------- launch ----------------
extern "C" void kernel_launch(void* const* d_in, const int* in_sizes, int n_in,
                              void* d_out, int out_size)
{
  const float* bb      = (const float*)d_in[0];
  const float* latent  = (const float*)d_in[1];
  const float* rrot    = (const float*)d_in[2];
  const float* rtrans  = (const float*)d_in[3];
  const float* Wemb0   = (const float*)d_in[4];
  const float* Wemb1   = (const float*)d_in[5];
  const float* We1s    = (const float*)d_in[6];
  const float* Wss     = (const float*)d_in[7];
  const float* Wds     = (const float*)d_in[8];
  const float* We2s    = (const float*)d_in[9];
  const float* Wvs     = (const float*)d_in[10];
  const float* W0s     = (const float*)d_in[11];
  const float* W1s     = (const float*)d_in[12];
  const float* Wu1s    = (const float*)d_in[13];
  const float* Wu2s    = (const float*)d_in[14];
  const float* Wp0     = (const float*)d_in[15];
  const float* Wt      = (const float*)d_in[16];
  const float* bt      = (const float*)d_in[17];
  const float* Wseq1   = (const float*)d_in[18];
  const float* bseq1   = (const float*)d_in[19];
  const float* Wseq2   = (const float*)d_in[20];
  const float* bseq2   = (const float*)d_in[21];
  const float* Wseq3   = (const float*)d_in[22];
  const float* bseq3   = (const float*)d_in[23];
  const float* lit_pos = (const float*)d_in[24];
  const float* Wchi    = (const float*)d_in[25];
  const float* Wpsi    = (const float*)d_in[26];
  const int*   bids    = (const int*)d_in[28];
  float* out = (float*)d_out;

  init_ranges_kernel<<<1, 32>>>();
  batch_range_kernel<<<(NRES+255)/256, 256>>>(bids);
  node_embed_kernel<<<1250, 256>>>(bb, latent, Wemb0, Wemb1);
  knn_kernel<<<1250, 256>>>(bids);
  edge_init_kernel<<<(NEDGE+255)/256, 256>>>();

  int cur = 0;
  for (int l = 0; l < NLAYERS; l++){
    precompA_kernel<<<1250, 256>>>(cur,
        Wss + l*HDIM*HDIM, Wds + l*HDIM*HDIM, Wvs + l*HDIM*HDIM);
    mp_phase1<<<1250, 256>>>(cur,
        We1s + l*EFD*HDIM, We2s + l*HDIM*HDIM,
        W0s + l*HDIM*HDIM, W1s + l*HDIM*HDIM,
        Wu1s + l*96*64);
    mp_phase2<<<1250, 256>>>(Wu1s + l*96*64, Wu2s + l*64*32);
    cur ^= 1;
  }

  decode_kernel<<<1250, 256>>>(cur, rrot, rtrans, Wp0, Wt, bt,
                               Wseq1, bseq1, Wseq2, bseq2, Wseq3, bseq3,
                               lit_pos, Wchi, Wpsi, out);
}